// round 6
// baseline (speedup 1.0000x reference)
#include <cuda_runtime.h>
#include <cuda_bf16.h>
#include <math.h>
#include <stdint.h>

// Problem constants: S=2048, D=1280, H=16, HD=80
// cu_seqlens = [0,512,1024,1536,2048] -> 4 segments of 512 (block-diagonal attn)
#define SEQ   2048
#define DIM   1280
#define NH    16
#define HDIM  80
#define HD2   96          // padded head dim (K%32==0 for scores GEMM)
#define NSEG  4
#define SEGL  512

typedef __nv_bfloat16 bf16;

// ---------------- device scratch (static, no allocations) ----------------
__device__ float g_qkv[SEQ * 3 * DIM];                 // QKV GEMM out [s][3840]
__device__ float g_scores[NH * SEQ * SEGL];            // [(h*2048+s)][512]

__device__ bf16 g_hid_hi[SEQ * DIM];
__device__ bf16 g_hid_lo[SEQ * DIM];
__device__ bf16 g_w1_hi[3 * DIM * DIM];
__device__ bf16 g_w1_lo[3 * DIM * DIM];
__device__ bf16 g_w2_hi[DIM * DIM];
__device__ bf16 g_w2_lo[DIM * DIM];

__device__ bf16 g_qhi[NH * SEQ * HD2];                 // [h*2048+s][96]
__device__ bf16 g_qlo[NH * SEQ * HD2];
__device__ bf16 g_khi[NH * SEQ * HD2];
__device__ bf16 g_klo[NH * SEQ * HD2];
__device__ bf16 g_vthi[NH * 128 * SEQ];                // [h][d(128 pad)][s]
__device__ bf16 g_vtlo[NH * 128 * SEQ];

__device__ bf16 g_phi[NH * SEQ * SEGL];                // softmax probs split
__device__ bf16 g_plo[NH * SEQ * SEGL];

__device__ bf16 g_aohi[SEQ * DIM];                     // attn out split [s][h*80+d]
__device__ bf16 g_aolo[SEQ * DIM];

// =========================== MMA helpers =================================
__device__ __forceinline__ uint32_t smem_u32(const void* p) {
    uint32_t a;
    asm("{ .reg .u64 t; cvta.to.shared.u64 t, %1; cvt.u32.u64 %0, t; }"
        : "=r"(a) : "l"(p));
    return a;
}
__device__ __forceinline__ void ldsm_x4(uint32_t addr, uint32_t* r) {
    asm volatile("ldmatrix.sync.aligned.m8n8.x4.shared.b16 {%0,%1,%2,%3}, [%4];"
                 : "=r"(r[0]), "=r"(r[1]), "=r"(r[2]), "=r"(r[3]) : "r"(addr));
}
__device__ __forceinline__ void mma16816(float* c, const uint32_t* a,
                                         uint32_t b0, uint32_t b1) {
    asm volatile(
        "mma.sync.aligned.m16n8k16.row.col.f32.bf16.bf16.f32 "
        "{%0,%1,%2,%3}, {%4,%5,%6,%7}, {%8,%9}, {%0,%1,%2,%3};"
        : "+f"(c[0]), "+f"(c[1]), "+f"(c[2]), "+f"(c[3])
        : "r"(a[0]), "r"(a[1]), "r"(a[2]), "r"(a[3]), "r"(b0), "r"(b1));
}
__device__ __forceinline__ void cp16(uint32_t saddr, const void* gptr) {
    asm volatile("cp.async.ca.shared.global [%0], [%1], 16;"
                 :: "r"(saddr), "l"(gptr));
}

// =========================================================================
// Generic batched TN GEMM, bf16x3 via mma.sync + 2-stage cp.async, BK=32.
// C[m,n] = alpha * sum_k (Ahi+Alo)[m,k]*(Bhi+Blo)[n,k]  (+bias[n])
// CTA 128x128, BK=32, 128 threads = 4 warps, warp tile 64x64, 2 CTAs/SM.
// Batch z: h = z>>2, g = z&3; offsets offX = Xbh*h + Xbg*g (elements).
// M%128==0, N%128==0 (grid), K%32==0 required. Cols >= Nvalid skipped.
// If Chi != nullptr: write bf16 hi/lo split instead of fp32.
// =========================================================================
#define SMROW 40                     // bf16 per smem row (32 used + 8 pad)
#define TILEB  (128 * SMROW * 2)     // 10240 B
#define STAGEB (4 * TILEB)           // 40960 B
#define GEMM_SMEM (2 * STAGEB)       // 81920 B

// 128 threads: each thread copies its row (64B = 4x cp16) per tile
#define ISSUE_STAGE(kc, st)                                               \
    do {                                                                  \
        const int      _ke = (kc) * 32;                                   \
        const uint32_t _s  = sb + (uint32_t)(st) * STAGEB + stoff;        \
        cp16(_s + 0 * TILEB,      gAh + _ke);                             \
        cp16(_s + 0 * TILEB + 16, gAh + _ke + 8);                         \
        cp16(_s + 0 * TILEB + 32, gAh + _ke + 16);                        \
        cp16(_s + 0 * TILEB + 48, gAh + _ke + 24);                        \
        cp16(_s + 1 * TILEB,      gAl + _ke);                             \
        cp16(_s + 1 * TILEB + 16, gAl + _ke + 8);                         \
        cp16(_s + 1 * TILEB + 32, gAl + _ke + 16);                        \
        cp16(_s + 1 * TILEB + 48, gAl + _ke + 24);                        \
        cp16(_s + 2 * TILEB,      gBh + _ke);                             \
        cp16(_s + 2 * TILEB + 16, gBh + _ke + 8);                         \
        cp16(_s + 2 * TILEB + 32, gBh + _ke + 16);                        \
        cp16(_s + 2 * TILEB + 48, gBh + _ke + 24);                        \
        cp16(_s + 3 * TILEB,      gBl + _ke);                             \
        cp16(_s + 3 * TILEB + 16, gBl + _ke + 8);                         \
        cp16(_s + 3 * TILEB + 32, gBl + _ke + 16);                        \
        cp16(_s + 3 * TILEB + 48, gBl + _ke + 24);                        \
        asm volatile("cp.async.commit_group;");                           \
    } while (0)

__global__ __launch_bounds__(128, 2)
void gemm_mma(const bf16* __restrict__ Ahi, const bf16* __restrict__ Alo,
              const bf16* __restrict__ Bhi, const bf16* __restrict__ Blo,
              const float* __restrict__ bias,
              float* __restrict__ C, bf16* __restrict__ Chi, bf16* __restrict__ Clo,
              int K, int lda, int ldb, int ldc, int Nvalid, float alpha,
              long Abh, long Abg, long Bbh, long Bbg, long Cbh, long Cbg)
{
    extern __shared__ __align__(16) char sm[];
    const uint32_t sb = smem_u32(sm);

    const int tid  = threadIdx.x;
    const int lane = tid & 31;
    const int wid  = tid >> 5;
    const int wm   = wid & 1;           // warp row (64 rows each)
    const int wn   = wid >> 1;          // warp col (64 cols each)

    const int h = blockIdx.z >> 2, g = blockIdx.z & 3;
    const size_t offA = (size_t)(Abh * h + Abg * g);
    const size_t offB = (size_t)(Bbh * h + Bbg * g);
    const size_t offC = (size_t)(Cbh * h + Cbg * g);

    const int m0 = blockIdx.y * 128;
    const int n0 = blockIdx.x * 128;

    // cp.async mapping: thread t handles row t of each 128-row tile
    const bf16* gAh = Ahi + offA + (size_t)(m0 + tid) * lda;
    const bf16* gAl = Alo + offA + (size_t)(m0 + tid) * lda;
    const bf16* gBh = Bhi + offB + (size_t)(n0 + tid) * ldb;
    const bf16* gBl = Blo + offB + (size_t)(n0 + tid) * ldb;
    const uint32_t stoff = (uint32_t)tid * (SMROW * 2);

    // ldmatrix fragment base addresses (row stride 80B: conflict-free phases)
    const uint32_t a_base = ((wm * 64 + (lane & 15)) * SMROW + (lane >> 4) * 8) * 2;
    const uint32_t b_base = ((wn * 64 + (lane & 15)) * SMROW + (lane >> 4) * 8) * 2;
    const uint32_t frag_step = 16 * SMROW * 2;   // 16 rows

    float acc[4][8][4];
#pragma unroll
    for (int i = 0; i < 4; i++)
#pragma unroll
        for (int j = 0; j < 8; j++)
#pragma unroll
            for (int l = 0; l < 4; l++) acc[i][j][l] = 0.f;

    const int nchunk = K >> 5;

    ISSUE_STAGE(0, 0);

    for (int kc = 0; kc < nchunk; kc++) {
        const int st = kc & 1;
        if (kc + 1 < nchunk) {
            ISSUE_STAGE(kc + 1, st ^ 1);
            asm volatile("cp.async.wait_group 1;");
        } else {
            asm volatile("cp.async.wait_group 0;");
        }
        __syncthreads();

        const uint32_t base = sb + (uint32_t)st * STAGEB;

#pragma unroll
        for (int ks = 0; ks < 2; ks++) {
            const uint32_t ko = ks * 32;   // +16 bf16 columns = 32 bytes

            uint32_t A_h[4][4], A_l[4][4], B[4][4];
#pragma unroll
            for (int mi = 0; mi < 4; mi++) {
                ldsm_x4(base + 0 * TILEB + a_base + ko + mi * frag_step, A_h[mi]);
                ldsm_x4(base + 1 * TILEB + a_base + ko + mi * frag_step, A_l[mi]);
            }
#pragma unroll
            for (int njg = 0; njg < 4; njg++)
                ldsm_x4(base + 2 * TILEB + b_base + ko + njg * frag_step, B[njg]);

            // pass 1: hi*hi  (32 independent MMAs)
#pragma unroll
            for (int mi = 0; mi < 4; mi++)
#pragma unroll
                for (int njg = 0; njg < 4; njg++) {
                    mma16816(acc[mi][2 * njg + 0], A_h[mi], B[njg][0], B[njg][2]);
                    mma16816(acc[mi][2 * njg + 1], A_h[mi], B[njg][1], B[njg][3]);
                }
            // pass 2: lo*hi
#pragma unroll
            for (int mi = 0; mi < 4; mi++)
#pragma unroll
                for (int njg = 0; njg < 4; njg++) {
                    mma16816(acc[mi][2 * njg + 0], A_l[mi], B[njg][0], B[njg][2]);
                    mma16816(acc[mi][2 * njg + 1], A_l[mi], B[njg][1], B[njg][3]);
                }
            // pass 3: hi*lo (reload B regs with Blo)
#pragma unroll
            for (int njg = 0; njg < 4; njg++)
                ldsm_x4(base + 3 * TILEB + b_base + ko + njg * frag_step, B[njg]);
#pragma unroll
            for (int mi = 0; mi < 4; mi++)
#pragma unroll
                for (int njg = 0; njg < 4; njg++) {
                    mma16816(acc[mi][2 * njg + 0], A_h[mi], B[njg][0], B[njg][2]);
                    mma16816(acc[mi][2 * njg + 1], A_h[mi], B[njg][1], B[njg][3]);
                }
        }
        __syncthreads();
    }

    // epilogue
#pragma unroll
    for (int mi = 0; mi < 4; mi++) {
        int row0 = m0 + wm * 64 + mi * 16 + (lane >> 2);
#pragma unroll
        for (int nj = 0; nj < 8; nj++) {
            int col = n0 + wn * 64 + nj * 8 + (lane & 3) * 2;
            if (col >= Nvalid) continue;
            float b0 = 0.f, b1 = 0.f;
            if (bias) { b0 = bias[col]; b1 = bias[col + 1]; }
            float v00 = acc[mi][nj][0] * alpha + b0;
            float v01 = acc[mi][nj][1] * alpha + b1;
            float v10 = acc[mi][nj][2] * alpha + b0;
            float v11 = acc[mi][nj][3] * alpha + b1;
            size_t i0 = offC + (size_t)row0 * ldc + col;
            size_t i1 = i0 + (size_t)8 * ldc;
            if (Chi) {
                bf16 h00 = __float2bfloat16(v00), h01 = __float2bfloat16(v01);
                bf16 h10 = __float2bfloat16(v10), h11 = __float2bfloat16(v11);
                *(__nv_bfloat162*)(Chi + i0) = __nv_bfloat162(h00, h01);
                *(__nv_bfloat162*)(Chi + i1) = __nv_bfloat162(h10, h11);
                *(__nv_bfloat162*)(Clo + i0) = __nv_bfloat162(
                    __float2bfloat16(v00 - __bfloat162float(h00)),
                    __float2bfloat16(v01 - __bfloat162float(h01)));
                *(__nv_bfloat162*)(Clo + i1) = __nv_bfloat162(
                    __float2bfloat16(v10 - __bfloat162float(h10)),
                    __float2bfloat16(v11 - __bfloat162float(h11)));
            } else {
                *(float2*)(C + i0) = make_float2(v00, v01);
                *(float2*)(C + i1) = make_float2(v10, v11);
            }
        }
    }
}

// =========================================================================
// Split fp32 -> bf16 hi + lo
// =========================================================================
__global__ void split_kernel(const float* __restrict__ x,
                             bf16* __restrict__ hi, bf16* __restrict__ lo, int n)
{
    int i = blockIdx.x * blockDim.x + threadIdx.x;
    if (i >= n) return;
    float v = x[i];
    bf16 h = __float2bfloat16(v);
    hi[i] = h;
    lo[i] = __float2bfloat16(v - __bfloat162float(h));
}

// =========================================================================
// RoPE + rearrange + split:
//  q,k -> [h*2048+s][96] bf16 hi/lo (rotated, cols 80..95 zeroed by pad krnl);
//  v -> transposed [h][d][s] hi/lo
// =========================================================================
__global__ void rope_kernel(const float* __restrict__ rope)
{
    int idx = blockIdx.x * blockDim.x + threadIdx.x;
    if (idx >= SEQ * NH * HDIM) return;
    int d = idx % HDIM;
    int h = (idx / HDIM) % NH;
    int s = idx / (NH * HDIM);

    float ang = rope[s * (HDIM / 2) + (d % (HDIM / 2))];
    float c, sn;
    __sincosf(ang, &sn, &c);

    const float* qrow = g_qkv + (long)s * (3 * DIM);
    int base = h * HDIM + d;
    float qv = qrow[base];
    float kv = qrow[DIM + base];
    float vv = qrow[2 * DIM + base];

    float qo, ko;
    if (d < HDIM / 2) {
        float q2 = qrow[base + HDIM / 2];
        float k2 = qrow[DIM + base + HDIM / 2];
        qo = qv * c - q2 * sn;
        ko = kv * c - k2 * sn;
    } else {
        float q2 = qrow[base - HDIM / 2];
        float k2 = qrow[DIM + base - HDIM / 2];
        qo = qv * c + q2 * sn;
        ko = kv * c + k2 * sn;
    }

    long o = (long)(h * SEQ + s) * HD2 + d;
    bf16 qh = __float2bfloat16(qo);
    bf16 kh = __float2bfloat16(ko);
    g_qhi[o] = qh;
    g_qlo[o] = __float2bfloat16(qo - __bfloat162float(qh));
    g_khi[o] = kh;
    g_klo[o] = __float2bfloat16(ko - __bfloat162float(kh));

    long ov = (long)h * 128 * SEQ + (long)d * SEQ + s;
    bf16 vh = __float2bfloat16(vv);
    g_vthi[ov] = vh;
    g_vtlo[ov] = __float2bfloat16(vv - __bfloat162float(vh));
}

// zero pads: q/k cols 80..95 (4 buffers) and vt rows 80..127 (2 buffers)
__global__ void pad_kernel()
{
    int idx = blockIdx.x * blockDim.x + threadIdx.x;
    const bf16 z = __float2bfloat16(0.f);
    int nqk = NH * SEQ * 16;              // per q/k buffer
    if (idx < nqk) {
        int d = 80 + (idx & 15);
        int hs = idx >> 4;
        long o = (long)hs * HD2 + d;
        g_qhi[o] = z; g_qlo[o] = z; g_khi[o] = z; g_klo[o] = z;
        return;
    }
    idx -= nqk;
    int nvt = NH * 48 * SEQ;
    if (idx >= nvt) return;
    int s = idx % SEQ;
    int d = 80 + (idx / SEQ) % 48;
    int h = idx / (SEQ * 48);
    long o = (long)h * 128 * SEQ + (long)d * SEQ + s;
    g_vthi[o] = z;
    g_vtlo[o] = z;
}

// =========================================================================
// Row softmax over 512 + fused bf16 hi/lo split of probabilities.
// =========================================================================
__global__ __launch_bounds__(128) void softmax_split(const float* __restrict__ S)
{
    long row = blockIdx.x;
    const float* p = S + row * SEGL;
    int tid = threadIdx.x;

    float4 v = ((const float4*)p)[tid];
    float m = fmaxf(fmaxf(v.x, v.y), fmaxf(v.z, v.w));

    __shared__ float red[4];
#pragma unroll
    for (int off = 16; off > 0; off >>= 1)
        m = fmaxf(m, __shfl_xor_sync(0xffffffffu, m, off));
    if ((tid & 31) == 0) red[tid >> 5] = m;
    __syncthreads();
    m = fmaxf(fmaxf(red[0], red[1]), fmaxf(red[2], red[3]));

    v.x = __expf(v.x - m); v.y = __expf(v.y - m);
    v.z = __expf(v.z - m); v.w = __expf(v.w - m);
    float sum = v.x + v.y + v.z + v.w;
#pragma unroll
    for (int off = 16; off > 0; off >>= 1)
        sum += __shfl_xor_sync(0xffffffffu, sum, off);
    __syncthreads();
    if ((tid & 31) == 0) red[tid >> 5] = sum;
    __syncthreads();
    sum = red[0] + red[1] + red[2] + red[3];

    float inv = 1.0f / sum;
    v.x *= inv; v.y *= inv; v.z *= inv; v.w *= inv;

    bf16 hx = __float2bfloat16(v.x), hy = __float2bfloat16(v.y);
    bf16 hz = __float2bfloat16(v.z), hw = __float2bfloat16(v.w);
    long o = row * SEGL + tid * 4;
    *(__nv_bfloat162*)(g_phi + o)     = __nv_bfloat162(hx, hy);
    *(__nv_bfloat162*)(g_phi + o + 2) = __nv_bfloat162(hz, hw);
    *(__nv_bfloat162*)(g_plo + o)     = __nv_bfloat162(
        __float2bfloat16(v.x - __bfloat162float(hx)),
        __float2bfloat16(v.y - __bfloat162float(hy)));
    *(__nv_bfloat162*)(g_plo + o + 2) = __nv_bfloat162(
        __float2bfloat16(v.z - __bfloat162float(hz)),
        __float2bfloat16(v.w - __bfloat162float(hw)));
}

// =========================================================================
extern "C" void kernel_launch(void* const* d_in, const int* in_sizes, int n_in,
                              void* d_out, int out_size)
{
    const float* hidden = (const float*)d_in[0];  // [2048,1280]
    const float* rope   = (const float*)d_in[2];  // [2048,40]
    const float* qkv_w  = (const float*)d_in[3];  // [3840,1280]
    const float* qkv_b  = (const float*)d_in[4];  // [3840]
    const float* proj_w = (const float*)d_in[5];  // [1280,1280]
    const float* proj_b = (const float*)d_in[6];  // [1280]
    float* out = (float*)d_out;                   // [2048,1280]

    float *qkv, *scores;
    cudaGetSymbolAddress((void**)&qkv,    g_qkv);
    cudaGetSymbolAddress((void**)&scores, g_scores);

    bf16 *hid_hi, *hid_lo, *w1_hi, *w1_lo, *w2_hi, *w2_lo;
    bf16 *qhi, *qlo, *khi, *klo, *vthi, *vtlo, *phi, *plo, *aohi, *aolo;
    cudaGetSymbolAddress((void**)&hid_hi, g_hid_hi);
    cudaGetSymbolAddress((void**)&hid_lo, g_hid_lo);
    cudaGetSymbolAddress((void**)&w1_hi,  g_w1_hi);
    cudaGetSymbolAddress((void**)&w1_lo,  g_w1_lo);
    cudaGetSymbolAddress((void**)&w2_hi,  g_w2_hi);
    cudaGetSymbolAddress((void**)&w2_lo,  g_w2_lo);
    cudaGetSymbolAddress((void**)&qhi,    g_qhi);
    cudaGetSymbolAddress((void**)&qlo,    g_qlo);
    cudaGetSymbolAddress((void**)&khi,    g_khi);
    cudaGetSymbolAddress((void**)&klo,    g_klo);
    cudaGetSymbolAddress((void**)&vthi,   g_vthi);
    cudaGetSymbolAddress((void**)&vtlo,   g_vtlo);
    cudaGetSymbolAddress((void**)&phi,    g_phi);
    cudaGetSymbolAddress((void**)&plo,    g_plo);
    cudaGetSymbolAddress((void**)&aohi,   g_aohi);
    cudaGetSymbolAddress((void**)&aolo,   g_aolo);

    static int smem_set = 0;
    if (!smem_set) {
        cudaFuncSetAttribute(gemm_mma,
                             cudaFuncAttributeMaxDynamicSharedMemorySize,
                             GEMM_SMEM);
        smem_set = 1;
    }

    // 0) splits for QKV / proj weights + hidden
    split_kernel<<<(SEQ * DIM + 255) / 256, 256>>>(hidden, hid_hi, hid_lo, SEQ * DIM);
    split_kernel<<<(3 * DIM * DIM + 255) / 256, 256>>>(qkv_w, w1_hi, w1_lo, 3 * DIM * DIM);
    split_kernel<<<(DIM * DIM + 255) / 256, 256>>>(proj_w, w2_hi, w2_lo, DIM * DIM);

    // 1) QKV GEMM: [2048,1280] x [3840,1280]^T + bias -> g_qkv (fp32)
    {
        dim3 grid(3 * DIM / 128, SEQ / 128, 1);
        gemm_mma<<<grid, 128, GEMM_SMEM>>>(hid_hi, hid_lo, w1_hi, w1_lo, qkv_b,
                                           qkv, nullptr, nullptr,
                                           DIM, DIM, DIM, 3 * DIM, 3 * DIM, 1.0f,
                                           0, 0, 0, 0, 0, 0);
    }

    // 2) RoPE + rearrange + split; zero pads
    rope_kernel<<<(SEQ * NH * HDIM + 255) / 256, 256>>>(rope);
    {
        int total = NH * SEQ * 16 + NH * 48 * SEQ;
        pad_kernel<<<(total + 255) / 256, 256>>>();
    }

    // 3) Scores: per (h,g): Q_g @ K_g^T / sqrt(80) -> g_scores (fp32), K=96 padded
    {
        dim3 grid(SEGL / 128, SEGL / 128, NH * NSEG);
        gemm_mma<<<grid, 128, GEMM_SMEM>>>(qhi, qlo, khi, klo, nullptr,
                                           scores, nullptr, nullptr,
                                           HD2, HD2, HD2, SEGL, SEGL,
                                           rsqrtf((float)HDIM),
                                           (long)4 * SEGL * HD2, (long)SEGL * HD2,
                                           (long)4 * SEGL * HD2, (long)SEGL * HD2,
                                           (long)4 * SEGL * SEGL, (long)SEGL * SEGL);
    }

    // 4) Softmax + split P to bf16 hi/lo
    softmax_split<<<NH * SEQ, 128>>>(scores);

    // 5) PV: P[512,512] @ Vt[128pad,512]^T -> attnout split [s][h*80+d]
    {
        dim3 grid(1, SEGL / 128, NH * NSEG);
        gemm_mma<<<grid, 128, GEMM_SMEM>>>(phi, plo, vthi, vtlo, nullptr,
                                           nullptr, aohi, aolo,
                                           SEGL, SEGL, SEQ, DIM, HDIM, 1.0f,
                                           (long)4 * SEGL * SEGL, (long)SEGL * SEGL,
                                           (long)128 * SEQ, (long)SEGL,
                                           (long)HDIM, (long)SEGL * DIM);
    }

    // 6) Proj: [2048,1280] x [1280,1280]^T + bias -> out (fp32)
    {
        dim3 grid(DIM / 128, SEQ / 128, 1);
        gemm_mma<<<grid, 128, GEMM_SMEM>>>(aohi, aolo, w2_hi, w2_lo, proj_b,
                                           out, nullptr, nullptr,
                                           DIM, DIM, DIM, DIM, DIM, 1.0f,
                                           0, 0, 0, 0, 0, 0);
    }
}

// round 7
// speedup vs baseline: 1.3158x; 1.3158x over previous
#include <cuda_runtime.h>
#include <cuda_bf16.h>
#include <math.h>
#include <stdint.h>

// Problem constants: S=2048, D=1280, H=16, HD=80
// cu_seqlens = [0,512,1024,1536,2048] -> 4 segments of 512 (block-diagonal attn)
#define SEQ   2048
#define DIM   1280
#define NH    16
#define HDIM  80
#define HD2   96          // padded head dim (K%32==0 for scores)
#define NSEG  4
#define SEGL  512

typedef __nv_bfloat16 bf16;

// ---------------- device scratch (static, no allocations) ----------------
__device__ float g_qkv[SEQ * 3 * DIM];                 // QKV GEMM out [s][3840]

__device__ bf16 g_hid_hi[SEQ * DIM];
__device__ bf16 g_hid_lo[SEQ * DIM];
__device__ bf16 g_w1_hi[3 * DIM * DIM];
__device__ bf16 g_w1_lo[3 * DIM * DIM];
__device__ bf16 g_w2_hi[DIM * DIM];
__device__ bf16 g_w2_lo[DIM * DIM];

__device__ bf16 g_qhi[NH * SEQ * HD2];                 // [h*2048+s][96] (q pre-scaled)
__device__ bf16 g_qlo[NH * SEQ * HD2];
__device__ bf16 g_khi[NH * SEQ * HD2];
__device__ bf16 g_klo[NH * SEQ * HD2];
__device__ bf16 g_vhi[NH * SEQ * HDIM];                // [h*2048+s][80]
__device__ bf16 g_vlo[NH * SEQ * HDIM];

__device__ bf16 g_aohi[SEQ * DIM];                     // attn out split [s][h*80+d]
__device__ bf16 g_aolo[SEQ * DIM];

// =========================== MMA helpers =================================
__device__ __forceinline__ uint32_t smem_u32(const void* p) {
    uint32_t a;
    asm("{ .reg .u64 t; cvta.to.shared.u64 t, %1; cvt.u32.u64 %0, t; }"
        : "=r"(a) : "l"(p));
    return a;
}
__device__ __forceinline__ void ldsm_x4(uint32_t addr, uint32_t* r) {
    asm volatile("ldmatrix.sync.aligned.m8n8.x4.shared.b16 {%0,%1,%2,%3}, [%4];"
                 : "=r"(r[0]), "=r"(r[1]), "=r"(r[2]), "=r"(r[3]) : "r"(addr));
}
__device__ __forceinline__ void ldsm_x4_t(uint32_t addr, uint32_t* r) {
    asm volatile("ldmatrix.sync.aligned.m8n8.x4.trans.shared.b16 {%0,%1,%2,%3}, [%4];"
                 : "=r"(r[0]), "=r"(r[1]), "=r"(r[2]), "=r"(r[3]) : "r"(addr));
}
__device__ __forceinline__ void mma16816(float* c, const uint32_t* a,
                                         uint32_t b0, uint32_t b1) {
    asm volatile(
        "mma.sync.aligned.m16n8k16.row.col.f32.bf16.bf16.f32 "
        "{%0,%1,%2,%3}, {%4,%5,%6,%7}, {%8,%9}, {%0,%1,%2,%3};"
        : "+f"(c[0]), "+f"(c[1]), "+f"(c[2]), "+f"(c[3])
        : "r"(a[0]), "r"(a[1]), "r"(a[2]), "r"(a[3]), "r"(b0), "r"(b1));
}
__device__ __forceinline__ void cp16(uint32_t saddr, const void* gptr) {
    asm volatile("cp.async.ca.shared.global [%0], [%1], 16;"
                 :: "r"(saddr), "l"(gptr));
}
__device__ __forceinline__ uint32_t packbf2(float x, float y) {
    __nv_bfloat162 h = __floats2bfloat162_rn(x, y);
    return *reinterpret_cast<uint32_t*>(&h);
}

// =========================================================================
// Generic batched TN GEMM (R5 config): bf16x3 mma.sync + 2-stage cp.async.
// CTA 128x128, BK=32, 256 threads = 8 warps (warp tile 32x64), 2 CTAs/SM.
// =========================================================================
#define SMROW 40                     // bf16 per smem row (32 used + 8 pad)
#define TILEB  (128 * SMROW * 2)     // 10240 B
#define STAGEB (4 * TILEB)           // 40960 B
#define GEMM_SMEM (2 * STAGEB)       // 81920 B

#define ISSUE_STAGE(kc, st)                                               \
    do {                                                                  \
        const int      _ke = (kc) * 32;                                   \
        const uint32_t _s  = sb + (uint32_t)(st) * STAGEB + stoff;        \
        cp16(_s + 0 * TILEB,      gAh + _ke);                             \
        cp16(_s + 0 * TILEB + 32, gAh + _ke + 16);                        \
        cp16(_s + 1 * TILEB,      gAl + _ke);                             \
        cp16(_s + 1 * TILEB + 32, gAl + _ke + 16);                        \
        cp16(_s + 2 * TILEB,      gBh + _ke);                             \
        cp16(_s + 2 * TILEB + 32, gBh + _ke + 16);                        \
        cp16(_s + 3 * TILEB,      gBl + _ke);                             \
        cp16(_s + 3 * TILEB + 32, gBl + _ke + 16);                        \
        asm volatile("cp.async.commit_group;");                           \
    } while (0)

__global__ __launch_bounds__(256, 2)
void gemm_mma(const bf16* __restrict__ Ahi, const bf16* __restrict__ Alo,
              const bf16* __restrict__ Bhi, const bf16* __restrict__ Blo,
              const float* __restrict__ bias, float* __restrict__ C,
              int K, int lda, int ldb, int ldc, float alpha)
{
    extern __shared__ __align__(16) char sm[];
    const uint32_t sb = smem_u32(sm);

    const int tid  = threadIdx.x;
    const int lane = tid & 31;
    const int wid  = tid >> 5;
    const int wm   = wid & 3;
    const int wn   = wid >> 2;

    const int m0 = blockIdx.y * 128;
    const int n0 = blockIdx.x * 128;

    const int r  = tid >> 1;
    const int hf = tid & 1;
    const bf16* gAh = Ahi + (size_t)(m0 + r) * lda + hf * 8;
    const bf16* gAl = Alo + (size_t)(m0 + r) * lda + hf * 8;
    const bf16* gBh = Bhi + (size_t)(n0 + r) * ldb + hf * 8;
    const bf16* gBl = Blo + (size_t)(n0 + r) * ldb + hf * 8;
    const uint32_t stoff = (uint32_t)(r * SMROW + hf * 8) * 2;

    const uint32_t a_off = ((wm * 32 + (lane & 15)) * SMROW + (lane >> 4) * 8) * 2;
    const uint32_t b_off = ((wn * 64 + (lane & 15)) * SMROW + (lane >> 4) * 8) * 2;

    float acc[2][8][4];
#pragma unroll
    for (int i = 0; i < 2; i++)
#pragma unroll
        for (int j = 0; j < 8; j++)
#pragma unroll
            for (int l = 0; l < 4; l++) acc[i][j][l] = 0.f;

    const int nchunk = K >> 5;

    ISSUE_STAGE(0, 0);

    for (int kc = 0; kc < nchunk; kc++) {
        const int st = kc & 1;
        if (kc + 1 < nchunk) {
            ISSUE_STAGE(kc + 1, st ^ 1);
            asm volatile("cp.async.wait_group 1;");
        } else {
            asm volatile("cp.async.wait_group 0;");
        }
        __syncthreads();

        const uint32_t base = sb + (uint32_t)st * STAGEB;

#pragma unroll
        for (int ks = 0; ks < 2; ks++) {
            const uint32_t ko = ks * 32;

            uint32_t A_h[2][4], A_l[2][4], B[4][4];
#pragma unroll
            for (int mi = 0; mi < 2; mi++) {
                ldsm_x4(base + 0 * TILEB + a_off + ko + mi * (16 * SMROW * 2), A_h[mi]);
                ldsm_x4(base + 1 * TILEB + a_off + ko + mi * (16 * SMROW * 2), A_l[mi]);
            }
#pragma unroll
            for (int njg = 0; njg < 4; njg++)
                ldsm_x4(base + 2 * TILEB + b_off + ko + njg * (16 * SMROW * 2), B[njg]);

#pragma unroll
            for (int mi = 0; mi < 2; mi++)
#pragma unroll
                for (int njg = 0; njg < 4; njg++) {
                    mma16816(acc[mi][2 * njg + 0], A_h[mi], B[njg][0], B[njg][2]);
                    mma16816(acc[mi][2 * njg + 1], A_h[mi], B[njg][1], B[njg][3]);
                }
#pragma unroll
            for (int mi = 0; mi < 2; mi++)
#pragma unroll
                for (int njg = 0; njg < 4; njg++) {
                    mma16816(acc[mi][2 * njg + 0], A_l[mi], B[njg][0], B[njg][2]);
                    mma16816(acc[mi][2 * njg + 1], A_l[mi], B[njg][1], B[njg][3]);
                }
#pragma unroll
            for (int njg = 0; njg < 4; njg++)
                ldsm_x4(base + 3 * TILEB + b_off + ko + njg * (16 * SMROW * 2), B[njg]);
#pragma unroll
            for (int mi = 0; mi < 2; mi++)
#pragma unroll
                for (int njg = 0; njg < 4; njg++) {
                    mma16816(acc[mi][2 * njg + 0], A_h[mi], B[njg][0], B[njg][2]);
                    mma16816(acc[mi][2 * njg + 1], A_h[mi], B[njg][1], B[njg][3]);
                }
        }
        __syncthreads();
    }

#pragma unroll
    for (int mi = 0; mi < 2; mi++) {
        int row0 = m0 + wm * 32 + mi * 16 + (lane >> 2);
#pragma unroll
        for (int nj = 0; nj < 8; nj++) {
            int col = n0 + wn * 64 + nj * 8 + (lane & 3) * 2;
            float b0 = 0.f, b1 = 0.f;
            if (bias) { b0 = bias[col]; b1 = bias[col + 1]; }
            size_t i0 = (size_t)row0 * ldc + col;
            size_t i1 = i0 + (size_t)8 * ldc;
            *(float2*)(C + i0) = make_float2(acc[mi][nj][0] * alpha + b0,
                                             acc[mi][nj][1] * alpha + b1);
            *(float2*)(C + i1) = make_float2(acc[mi][nj][2] * alpha + b0,
                                             acc[mi][nj][3] * alpha + b1);
        }
    }
}

// =========================================================================
// Fused flash attention (block-diagonal): one CTA per (h, g, 128 q-rows).
// 256 threads = 8 warps; warp w owns q-rows [w*16, w*16+16) x all 512 keys.
// bf16x3 for both Q.K^T and P.V; softmax online in fp32 registers.
// Output written as bf16 hi/lo split to g_aohi/g_aolo [s][h*80+d].
// =========================================================================
#define AQSTR 104                       // smem row stride (bf16): 96/80 used + pad
#define AROWB (AQSTR * 2)               // 208 bytes
#define ABUF  (128 * AROWB)             // 26624 B per buffer
#define SQH   0
#define SQL   (1 * ABUF)
#define SKH   (2 * ABUF)
#define SKL   (3 * ABUF)
#define SVH   (4 * ABUF)
#define SVL   (5 * ABUF)
#define ATT_SMEM (6 * ABUF)             // 159744 B

__global__ __launch_bounds__(256, 1)
void attn_fused()
{
    extern __shared__ __align__(16) char sm[];
    const uint32_t sb = smem_u32(sm);

    const int tid  = threadIdx.x;
    const int lane = tid & 31;
    const int wid  = tid >> 5;

    const int mt = blockIdx.x;          // 0..3 (q tile within segment)
    const int g  = blockIdx.y;          // 0..3 (segment)
    const int h  = blockIdx.z;          // 0..15 (head)

    const size_t segrow = (size_t)(h * SEQ + g * SEGL);
    const size_t qrow0  = segrow + mt * 128;

    // ---- prologue: load Q tile + K/V tile 0 ----
    {
        const int idx6 = tid;           // Q/K: 1536 chunks, 6 per thread
#pragma unroll
        for (int i = 0; i < 6; i++) {
            int idx = i * 256 + idx6;
            int rr = idx / 12, cc = idx % 12;
            uint32_t d = (uint32_t)(rr * AROWB + cc * 16);
            const size_t o = (qrow0 + rr) * HD2 + cc * 8;
            cp16(sb + SQH + d, g_qhi + o);
            cp16(sb + SQL + d, g_qlo + o);
            const size_t ok = (segrow + rr) * HD2 + cc * 8;
            cp16(sb + SKH + d, g_khi + ok);
            cp16(sb + SKL + d, g_klo + ok);
        }
#pragma unroll
        for (int i = 0; i < 5; i++) {
            int idx = i * 256 + tid;
            int rr = idx / 10, cc = idx % 10;
            uint32_t d = (uint32_t)(rr * AROWB + cc * 16);
            const size_t o = (segrow + rr) * HDIM + cc * 8;
            cp16(sb + SVH + d, g_vhi + o);
            cp16(sb + SVL + d, g_vlo + o);
        }
        asm volatile("cp.async.commit_group;");
        asm volatile("cp.async.wait_group 0;");
    }
    __syncthreads();

    // ---- load Q fragments (persistent across k-tiles) ----
    const uint32_t aq = ((wid * 16 + (lane & 15)) * AQSTR + (lane >> 4) * 8) * 2;
    uint32_t Qh[6][4], Ql[6][4];
#pragma unroll
    for (int kf = 0; kf < 6; kf++) {
        ldsm_x4(sb + SQH + aq + kf * 32, Qh[kf]);
        ldsm_x4(sb + SQL + aq + kf * 32, Ql[kf]);
    }

    float O[10][4];
#pragma unroll
    for (int f = 0; f < 10; f++)
#pragma unroll
        for (int l = 0; l < 4; l++) O[f][l] = 0.f;
    float mrow0 = -1e30f, mrow1 = -1e30f;
    float lrow0 = 0.f, lrow1 = 0.f;

    const uint32_t kb = (((lane & 15)) * AQSTR + (lane >> 4) * 8) * 2;

    for (int kt = 0; kt < 4; kt++) {
        // ---- scores: S = (Qh+Ql).(Kh+Kl)^T (3-pass), 16x128 per warp ----
        float S[16][4];
#pragma unroll
        for (int f = 0; f < 16; f++)
#pragma unroll
            for (int l = 0; l < 4; l++) S[f][l] = 0.f;

#pragma unroll
        for (int j = 0; j < 8; j++) {
            const uint32_t kaddr = kb + (uint32_t)(j * 16 * AROWB);
            uint32_t Bh[4], Bl[4];
#pragma unroll
            for (int kf = 0; kf < 6; kf++) {
                ldsm_x4(sb + SKH + kaddr + kf * 32, Bh);
                ldsm_x4(sb + SKL + kaddr + kf * 32, Bl);
                mma16816(S[2 * j + 0], Qh[kf], Bh[0], Bh[2]);
                mma16816(S[2 * j + 1], Qh[kf], Bh[1], Bh[3]);
                mma16816(S[2 * j + 0], Ql[kf], Bh[0], Bh[2]);
                mma16816(S[2 * j + 1], Ql[kf], Bh[1], Bh[3]);
                mma16816(S[2 * j + 0], Qh[kf], Bl[0], Bl[2]);
                mma16816(S[2 * j + 1], Qh[kf], Bl[1], Bl[3]);
            }
        }

        // ---- online softmax over this 128-key tile ----
        float t0 = -1e30f, t1 = -1e30f;
#pragma unroll
        for (int f = 0; f < 16; f++) {
            t0 = fmaxf(t0, fmaxf(S[f][0], S[f][1]));
            t1 = fmaxf(t1, fmaxf(S[f][2], S[f][3]));
        }
        t0 = fmaxf(t0, __shfl_xor_sync(0xffffffffu, t0, 1));
        t0 = fmaxf(t0, __shfl_xor_sync(0xffffffffu, t0, 2));
        t1 = fmaxf(t1, __shfl_xor_sync(0xffffffffu, t1, 1));
        t1 = fmaxf(t1, __shfl_xor_sync(0xffffffffu, t1, 2));

        float m0n = fmaxf(mrow0, t0);
        float m1n = fmaxf(mrow1, t1);
        float sc0 = __expf(mrow0 - m0n);
        float sc1 = __expf(mrow1 - m1n);
        mrow0 = m0n; mrow1 = m1n;

        float s0 = 0.f, s1 = 0.f;
#pragma unroll
        for (int f = 0; f < 16; f++) {
            S[f][0] = __expf(S[f][0] - m0n); s0 += S[f][0];
            S[f][1] = __expf(S[f][1] - m0n); s0 += S[f][1];
            S[f][2] = __expf(S[f][2] - m1n); s1 += S[f][2];
            S[f][3] = __expf(S[f][3] - m1n); s1 += S[f][3];
        }
        s0 += __shfl_xor_sync(0xffffffffu, s0, 1);
        s0 += __shfl_xor_sync(0xffffffffu, s0, 2);
        s1 += __shfl_xor_sync(0xffffffffu, s1, 1);
        s1 += __shfl_xor_sync(0xffffffffu, s1, 2);
        lrow0 = lrow0 * sc0 + s0;
        lrow1 = lrow1 * sc1 + s1;

#pragma unroll
        for (int f = 0; f < 10; f++) {
            O[f][0] *= sc0; O[f][1] *= sc0;
            O[f][2] *= sc1; O[f][3] *= sc1;
        }

        // ---- repack P (fp32 acc frags) -> bf16 hi/lo A-operand frags ----
        uint32_t Ph[8][4], Pl[8][4];
#pragma unroll
        for (int t = 0; t < 8; t++) {
#pragma unroll
            for (int q = 0; q < 4; q++) {
                float x = S[2 * t + (q >> 1)][(q & 1) * 2 + 0 + ((q & 1) ? 0 : 0)];
                (void)x;
            }
            // a0 = frag 2t (c0,c1); a1 = frag 2t (c2,c3);
            // a2 = frag 2t+1 (c0,c1); a3 = frag 2t+1 (c2,c3)
            float c00 = S[2 * t + 0][0], c01 = S[2 * t + 0][1];
            float c02 = S[2 * t + 0][2], c03 = S[2 * t + 0][3];
            float c10 = S[2 * t + 1][0], c11 = S[2 * t + 1][1];
            float c12 = S[2 * t + 1][2], c13 = S[2 * t + 1][3];
            Ph[t][0] = packbf2(c00, c01);
            Ph[t][1] = packbf2(c02, c03);
            Ph[t][2] = packbf2(c10, c11);
            Ph[t][3] = packbf2(c12, c13);
            __nv_bfloat162* hp;
            hp = (__nv_bfloat162*)&Ph[t][0];
            Pl[t][0] = packbf2(c00 - __bfloat162float(hp->x), c01 - __bfloat162float(hp->y));
            hp = (__nv_bfloat162*)&Ph[t][1];
            Pl[t][1] = packbf2(c02 - __bfloat162float(hp->x), c03 - __bfloat162float(hp->y));
            hp = (__nv_bfloat162*)&Ph[t][2];
            Pl[t][2] = packbf2(c10 - __bfloat162float(hp->x), c11 - __bfloat162float(hp->y));
            hp = (__nv_bfloat162*)&Ph[t][3];
            Pl[t][3] = packbf2(c12 - __bfloat162float(hp->x), c13 - __bfloat162float(hp->y));
        }

        // ---- PV: O += (Ph+Pl).(Vh+Vl), V via trans ldmatrix ----
#pragma unroll
        for (int jn = 0; jn < 5; jn++) {
#pragma unroll
            for (int kf = 0; kf < 8; kf++) {
                const uint32_t vaddr =
                    (uint32_t)((kf * 16 + (lane & 15)) * AQSTR +
                               jn * 16 + (lane >> 4) * 8) * 2;
                uint32_t Vh[4], Vl[4];
                ldsm_x4_t(sb + SVH + vaddr, Vh);
                ldsm_x4_t(sb + SVL + vaddr, Vl);
                mma16816(O[2 * jn + 0], Ph[kf], Vh[0], Vh[1]);
                mma16816(O[2 * jn + 1], Ph[kf], Vh[2], Vh[3]);
                mma16816(O[2 * jn + 0], Pl[kf], Vh[0], Vh[1]);
                mma16816(O[2 * jn + 1], Pl[kf], Vh[2], Vh[3]);
                mma16816(O[2 * jn + 0], Ph[kf], Vl[0], Vl[1]);
                mma16816(O[2 * jn + 1], Ph[kf], Vl[2], Vl[3]);
            }
        }

        // ---- load next K/V tile ----
        if (kt < 3) {
            __syncthreads();
            const size_t krow = segrow + (kt + 1) * 128;
#pragma unroll
            for (int i = 0; i < 6; i++) {
                int idx = i * 256 + tid;
                int rr = idx / 12, cc = idx % 12;
                uint32_t d = (uint32_t)(rr * AROWB + cc * 16);
                const size_t ok = (krow + rr) * HD2 + cc * 8;
                cp16(sb + SKH + d, g_khi + ok);
                cp16(sb + SKL + d, g_klo + ok);
            }
#pragma unroll
            for (int i = 0; i < 5; i++) {
                int idx = i * 256 + tid;
                int rr = idx / 10, cc = idx % 10;
                uint32_t d = (uint32_t)(rr * AROWB + cc * 16);
                const size_t o = (krow + rr) * HDIM + cc * 8;
                cp16(sb + SVH + d, g_vhi + o);
                cp16(sb + SVL + d, g_vlo + o);
            }
            asm volatile("cp.async.commit_group;");
            asm volatile("cp.async.wait_group 0;");
            __syncthreads();
        }
    }

    // ---- epilogue: O /= l, split to bf16 hi/lo, write [s][h*80+d] ----
    const float inv0 = 1.f / lrow0;
    const float inv1 = 1.f / lrow1;
    const int row0 = g * SEGL + mt * 128 + wid * 16 + (lane >> 2);
    const int row1 = row0 + 8;
#pragma unroll
    for (int f = 0; f < 10; f++) {
        int col = h * HDIM + f * 8 + (lane & 3) * 2;
        float v00 = O[f][0] * inv0, v01 = O[f][1] * inv0;
        float v10 = O[f][2] * inv1, v11 = O[f][3] * inv1;
        uint32_t h0 = packbf2(v00, v01);
        uint32_t h1 = packbf2(v10, v11);
        __nv_bfloat162* hp0 = (__nv_bfloat162*)&h0;
        __nv_bfloat162* hp1 = (__nv_bfloat162*)&h1;
        uint32_t l0 = packbf2(v00 - __bfloat162float(hp0->x),
                              v01 - __bfloat162float(hp0->y));
        uint32_t l1 = packbf2(v10 - __bfloat162float(hp1->x),
                              v11 - __bfloat162float(hp1->y));
        *(uint32_t*)(g_aohi + (size_t)row0 * DIM + col) = h0;
        *(uint32_t*)(g_aohi + (size_t)row1 * DIM + col) = h1;
        *(uint32_t*)(g_aolo + (size_t)row0 * DIM + col) = l0;
        *(uint32_t*)(g_aolo + (size_t)row1 * DIM + col) = l1;
    }
}

// =========================================================================
// Split fp32 -> bf16 hi + lo
// =========================================================================
__global__ void split_kernel(const float* __restrict__ x,
                             bf16* __restrict__ hi, bf16* __restrict__ lo, int n)
{
    int i = blockIdx.x * blockDim.x + threadIdx.x;
    if (i >= n) return;
    float v = x[i];
    bf16 h = __float2bfloat16(v);
    hi[i] = h;
    lo[i] = __float2bfloat16(v - __bfloat162float(h));
}

// =========================================================================
// RoPE + rearrange + split. q pre-scaled by 1/sqrt(80).
// =========================================================================
__global__ void rope_kernel(const float* __restrict__ rope)
{
    int idx = blockIdx.x * blockDim.x + threadIdx.x;
    if (idx >= SEQ * NH * HDIM) return;
    int d = idx % HDIM;
    int h = (idx / HDIM) % NH;
    int s = idx / (NH * HDIM);

    float ang = rope[s * (HDIM / 2) + (d % (HDIM / 2))];
    float c, sn;
    __sincosf(ang, &sn, &c);

    const float* qrow = g_qkv + (long)s * (3 * DIM);
    int base = h * HDIM + d;
    float qv = qrow[base];
    float kv = qrow[DIM + base];
    float vv = qrow[2 * DIM + base];

    float qo, ko;
    if (d < HDIM / 2) {
        float q2 = qrow[base + HDIM / 2];
        float k2 = qrow[DIM + base + HDIM / 2];
        qo = qv * c - q2 * sn;
        ko = kv * c - k2 * sn;
    } else {
        float q2 = qrow[base - HDIM / 2];
        float k2 = qrow[DIM + base - HDIM / 2];
        qo = qv * c + q2 * sn;
        ko = kv * c + k2 * sn;
    }
    qo *= 0.11180339887498949f;   // 1/sqrt(80), folded into q

    long o = (long)(h * SEQ + s) * HD2 + d;
    bf16 qh = __float2bfloat16(qo);
    bf16 kh = __float2bfloat16(ko);
    g_qhi[o] = qh;
    g_qlo[o] = __float2bfloat16(qo - __bfloat162float(qh));
    g_khi[o] = kh;
    g_klo[o] = __float2bfloat16(ko - __bfloat162float(kh));

    long ov = (long)(h * SEQ + s) * HDIM + d;
    bf16 vh = __float2bfloat16(vv);
    g_vhi[ov] = vh;
    g_vlo[ov] = __float2bfloat16(vv - __bfloat162float(vh));
}

// zero pads: q/k cols 80..95
__global__ void pad_kernel()
{
    int idx = blockIdx.x * blockDim.x + threadIdx.x;
    const bf16 z = __float2bfloat16(0.f);
    int nqk = NH * SEQ * 16;
    if (idx >= nqk) return;
    int d = 80 + (idx & 15);
    int hs = idx >> 4;
    long o = (long)hs * HD2 + d;
    g_qhi[o] = z; g_qlo[o] = z; g_khi[o] = z; g_klo[o] = z;
}

// =========================================================================
extern "C" void kernel_launch(void* const* d_in, const int* in_sizes, int n_in,
                              void* d_out, int out_size)
{
    const float* hidden = (const float*)d_in[0];  // [2048,1280]
    const float* rope   = (const float*)d_in[2];  // [2048,40]
    const float* qkv_w  = (const float*)d_in[3];  // [3840,1280]
    const float* qkv_b  = (const float*)d_in[4];  // [3840]
    const float* proj_w = (const float*)d_in[5];  // [1280,1280]
    const float* proj_b = (const float*)d_in[6];  // [1280]
    float* out = (float*)d_out;                   // [2048,1280]

    float* qkv;
    cudaGetSymbolAddress((void**)&qkv, g_qkv);

    bf16 *hid_hi, *hid_lo, *w1_hi, *w1_lo, *w2_hi, *w2_lo, *aohi, *aolo;
    cudaGetSymbolAddress((void**)&hid_hi, g_hid_hi);
    cudaGetSymbolAddress((void**)&hid_lo, g_hid_lo);
    cudaGetSymbolAddress((void**)&w1_hi,  g_w1_hi);
    cudaGetSymbolAddress((void**)&w1_lo,  g_w1_lo);
    cudaGetSymbolAddress((void**)&w2_hi,  g_w2_hi);
    cudaGetSymbolAddress((void**)&w2_lo,  g_w2_lo);
    cudaGetSymbolAddress((void**)&aohi,   g_aohi);
    cudaGetSymbolAddress((void**)&aolo,   g_aolo);

    static int attr_set = 0;
    if (!attr_set) {
        cudaFuncSetAttribute(gemm_mma,
                             cudaFuncAttributeMaxDynamicSharedMemorySize,
                             GEMM_SMEM);
        cudaFuncSetAttribute(attn_fused,
                             cudaFuncAttributeMaxDynamicSharedMemorySize,
                             ATT_SMEM);
        attr_set = 1;
    }

    // 0) splits for QKV / proj weights + hidden
    split_kernel<<<(SEQ * DIM + 255) / 256, 256>>>(hidden, hid_hi, hid_lo, SEQ * DIM);
    split_kernel<<<(3 * DIM * DIM + 255) / 256, 256>>>(qkv_w, w1_hi, w1_lo, 3 * DIM * DIM);
    split_kernel<<<(DIM * DIM + 255) / 256, 256>>>(proj_w, w2_hi, w2_lo, DIM * DIM);

    // 1) QKV GEMM: [2048,1280] x [3840,1280]^T + bias -> g_qkv (fp32)
    {
        dim3 grid(3 * DIM / 128, SEQ / 128, 1);
        gemm_mma<<<grid, 256, GEMM_SMEM>>>(hid_hi, hid_lo, w1_hi, w1_lo, qkv_b,
                                           qkv, DIM, DIM, DIM, 3 * DIM, 1.0f);
    }

    // 2) RoPE + rearrange + split; zero q/k pads
    rope_kernel<<<(SEQ * NH * HDIM + 255) / 256, 256>>>(rope);
    pad_kernel<<<(NH * SEQ * 16 + 255) / 256, 256>>>();

    // 3) Fused attention: scores + softmax + PV -> aohi/aolo
    {
        dim3 grid(4, NSEG, NH);
        attn_fused<<<grid, 256, ATT_SMEM>>>();
    }

    // 4) Proj: [2048,1280] x [1280,1280]^T + bias -> out (fp32)
    {
        dim3 grid(DIM / 128, SEQ / 128, 1);
        gemm_mma<<<grid, 256, GEMM_SMEM>>>(aohi, aolo, w2_hi, w2_lo, proj_b,
                                           out, DIM, DIM, DIM, DIM, 1.0f);
    }
}

// round 8
// speedup vs baseline: 2.7575x; 2.0957x over previous
#include <cuda_runtime.h>
#include <cuda_fp16.h>
#include <math.h>
#include <stdint.h>

// Problem constants: S=2048, D=1280, H=16, HD=80
// cu_seqlens = [0,512,1024,1536,2048] -> 4 segments of 512 (block-diagonal attn)
#define SEQ   2048
#define DIM   1280
#define NH    16
#define HDIM  80
#define NSEG  4
#define SEGL  512

// ---------------- device scratch (static, no allocations) ----------------
__device__ float g_qkv[SEQ * 3 * DIM];          // QKV GEMM out [s][3840] fp32
__device__ half  g_hid[SEQ * DIM];              // hidden fp16
__device__ half  g_w1[3 * DIM * DIM];           // qkv_w fp16
__device__ half  g_w2[DIM * DIM];               // proj_w fp16
__device__ half  g_q[NH * SEQ * HDIM];          // [h*2048+s][80], q pre-scaled
__device__ half  g_k[NH * SEQ * HDIM];
__device__ half  g_v[NH * SEQ * HDIM];
__device__ half  g_ao[SEQ * DIM];               // attn out [s][h*80+d] fp16

// =========================== MMA helpers =================================
__device__ __forceinline__ uint32_t smem_u32(const void* p) {
    uint32_t a;
    asm("{ .reg .u64 t; cvta.to.shared.u64 t, %1; cvt.u32.u64 %0, t; }"
        : "=r"(a) : "l"(p));
    return a;
}
__device__ __forceinline__ void ldsm_x4(uint32_t addr, uint32_t* r) {
    asm volatile("ldmatrix.sync.aligned.m8n8.x4.shared.b16 {%0,%1,%2,%3}, [%4];"
                 : "=r"(r[0]), "=r"(r[1]), "=r"(r[2]), "=r"(r[3]) : "r"(addr));
}
__device__ __forceinline__ void ldsm_x4_t(uint32_t addr, uint32_t* r) {
    asm volatile("ldmatrix.sync.aligned.m8n8.x4.trans.shared.b16 {%0,%1,%2,%3}, [%4];"
                 : "=r"(r[0]), "=r"(r[1]), "=r"(r[2]), "=r"(r[3]) : "r"(addr));
}
__device__ __forceinline__ void mma16816(float* c, const uint32_t* a,
                                         uint32_t b0, uint32_t b1) {
    asm volatile(
        "mma.sync.aligned.m16n8k16.row.col.f32.f16.f16.f32 "
        "{%0,%1,%2,%3}, {%4,%5,%6,%7}, {%8,%9}, {%0,%1,%2,%3};"
        : "+f"(c[0]), "+f"(c[1]), "+f"(c[2]), "+f"(c[3])
        : "r"(a[0]), "r"(a[1]), "r"(a[2]), "r"(a[3]), "r"(b0), "r"(b1));
}
__device__ __forceinline__ void cp16(uint32_t saddr, const void* gptr) {
    asm volatile("cp.async.ca.shared.global [%0], [%1], 16;"
                 :: "r"(saddr), "l"(gptr));
}
__device__ __forceinline__ uint32_t packh2(float x, float y) {
    __half2 h = __floats2half2_rn(x, y);
    return *reinterpret_cast<uint32_t*>(&h);
}

// =========================================================================
// fp16 TN GEMM: C[m,n] = sum_k A[m,k]*B[n,k] + bias[n]  (fp32 accum)
// CTA 128x128, BK=32, 256 threads = 8 warps (warp tile 32x64),
// 2-stage cp.async, 2 CTAs/SM. M%128==0, N%128==0, K%32==0.
// =========================================================================
#define SMROW 40                     // half per smem row (32 used + 8 pad)
#define TILEB  (128 * SMROW * 2)     // 10240 B
#define STAGEB (2 * TILEB)           // 20480 B (A + B)
#define GEMM_SMEM (2 * STAGEB)       // 40960 B

#define ISSUE_STAGE(kc, st)                                               \
    do {                                                                  \
        const int      _ke = (kc) * 32;                                   \
        const uint32_t _s  = sb + (uint32_t)(st) * STAGEB + stoff;        \
        cp16(_s + 0 * TILEB,      gA + _ke);                              \
        cp16(_s + 0 * TILEB + 32, gA + _ke + 16);                         \
        cp16(_s + 1 * TILEB,      gB + _ke);                              \
        cp16(_s + 1 * TILEB + 32, gB + _ke + 16);                         \
        asm volatile("cp.async.commit_group;");                           \
    } while (0)

__global__ __launch_bounds__(256, 2)
void gemm_fp16(const half* __restrict__ A, const half* __restrict__ B,
               const float* __restrict__ bias, float* __restrict__ C,
               int K, int lda, int ldb, int ldc)
{
    extern __shared__ __align__(16) char sm[];
    const uint32_t sb = smem_u32(sm);

    const int tid  = threadIdx.x;
    const int lane = tid & 31;
    const int wid  = tid >> 5;
    const int wm   = wid & 3;
    const int wn   = wid >> 2;

    const int m0 = blockIdx.y * 128;
    const int n0 = blockIdx.x * 128;

    const int r  = tid >> 1;
    const int hf = tid & 1;
    const half* gA = A + (size_t)(m0 + r) * lda + hf * 8;
    const half* gB = B + (size_t)(n0 + r) * ldb + hf * 8;
    const uint32_t stoff = (uint32_t)(r * SMROW + hf * 8) * 2;

    const uint32_t a_off = ((wm * 32 + (lane & 15)) * SMROW + (lane >> 4) * 8) * 2;
    const uint32_t b_off = ((wn * 64 + (lane & 15)) * SMROW + (lane >> 4) * 8) * 2;

    float acc[2][8][4];
#pragma unroll
    for (int i = 0; i < 2; i++)
#pragma unroll
        for (int j = 0; j < 8; j++)
#pragma unroll
            for (int l = 0; l < 4; l++) acc[i][j][l] = 0.f;

    const int nchunk = K >> 5;

    ISSUE_STAGE(0, 0);

    for (int kc = 0; kc < nchunk; kc++) {
        const int st = kc & 1;
        if (kc + 1 < nchunk) {
            ISSUE_STAGE(kc + 1, st ^ 1);
            asm volatile("cp.async.wait_group 1;");
        } else {
            asm volatile("cp.async.wait_group 0;");
        }
        __syncthreads();

        const uint32_t base = sb + (uint32_t)st * STAGEB;

#pragma unroll
        for (int ks = 0; ks < 2; ks++) {
            const uint32_t ko = ks * 32;

            uint32_t Af[2][4], Bf[4][4];
#pragma unroll
            for (int mi = 0; mi < 2; mi++)
                ldsm_x4(base + 0 * TILEB + a_off + ko + mi * (16 * SMROW * 2), Af[mi]);
#pragma unroll
            for (int njg = 0; njg < 4; njg++)
                ldsm_x4(base + 1 * TILEB + b_off + ko + njg * (16 * SMROW * 2), Bf[njg]);

#pragma unroll
            for (int mi = 0; mi < 2; mi++)
#pragma unroll
                for (int njg = 0; njg < 4; njg++) {
                    mma16816(acc[mi][2 * njg + 0], Af[mi], Bf[njg][0], Bf[njg][2]);
                    mma16816(acc[mi][2 * njg + 1], Af[mi], Bf[njg][1], Bf[njg][3]);
                }
        }
        __syncthreads();
    }

#pragma unroll
    for (int mi = 0; mi < 2; mi++) {
        int row0 = m0 + wm * 32 + mi * 16 + (lane >> 2);
#pragma unroll
        for (int nj = 0; nj < 8; nj++) {
            int col = n0 + wn * 64 + nj * 8 + (lane & 3) * 2;
            float b0 = 0.f, b1 = 0.f;
            if (bias) { b0 = bias[col]; b1 = bias[col + 1]; }
            size_t i0 = (size_t)row0 * ldc + col;
            size_t i1 = i0 + (size_t)8 * ldc;
            *(float2*)(C + i0) = make_float2(acc[mi][nj][0] + b0,
                                             acc[mi][nj][1] + b1);
            *(float2*)(C + i1) = make_float2(acc[mi][nj][2] + b0,
                                             acc[mi][nj][3] + b1);
        }
    }
}

// =========================================================================
// Fused flash attention (block-diagonal): one CTA per (h, g, 128 q-rows).
// 256 threads = 8 warps; warp w owns q-rows [w*16, w*16+16) x all 512 keys.
// Single-pass fp16 MMAs; softmax online in fp32 registers.
// Output fp16 to g_ao [s][h*80+d].
// =========================================================================
#define AQSTR 88                        // half per smem row (80 used + 8 pad)
#define AROWB (AQSTR * 2)               // 176 B
#define ABUF  (128 * AROWB)             // 22528 B
#define SQ    0
#define SK    (1 * ABUF)
#define SV    (2 * ABUF)
#define ATT_SMEM (3 * ABUF)             // 67584 B

__global__ __launch_bounds__(256, 1)
void attn_fused()
{
    extern __shared__ __align__(16) char sm[];
    const uint32_t sb = smem_u32(sm);

    const int tid  = threadIdx.x;
    const int lane = tid & 31;
    const int wid  = tid >> 5;

    const int mt = blockIdx.x;          // 0..3 (q tile within segment)
    const int g  = blockIdx.y;          // 0..3 (segment)
    const int h  = blockIdx.z;          // 0..15 (head)

    const size_t segrow = (size_t)(h * SEQ + g * SEGL);
    const size_t qrow0  = segrow + mt * 128;

    // ---- prologue: load Q tile + K/V tile 0 (128 rows x 80 half each) ----
#pragma unroll
    for (int i = 0; i < 5; i++) {
        int idx = i * 256 + tid;
        int rr = idx / 10, cc = idx % 10;
        uint32_t d = (uint32_t)(rr * AROWB + cc * 16);
        cp16(sb + SQ + d, g_q + (qrow0 + rr) * HDIM + cc * 8);
        cp16(sb + SK + d, g_k + (segrow + rr) * HDIM + cc * 8);
        cp16(sb + SV + d, g_v + (segrow + rr) * HDIM + cc * 8);
    }
    asm volatile("cp.async.commit_group;");
    asm volatile("cp.async.wait_group 0;");
    __syncthreads();

    // ---- load Q fragments (persistent across k-tiles), kf = 5 x 16 cols ----
    const uint32_t aq = ((wid * 16 + (lane & 15)) * AQSTR + (lane >> 4) * 8) * 2;
    uint32_t Qf[5][4];
#pragma unroll
    for (int kf = 0; kf < 5; kf++)
        ldsm_x4(sb + SQ + aq + kf * 32, Qf[kf]);

    float O[10][4];
#pragma unroll
    for (int f = 0; f < 10; f++)
#pragma unroll
        for (int l = 0; l < 4; l++) O[f][l] = 0.f;
    float mrow0 = -1e30f, mrow1 = -1e30f;
    float lrow0 = 0.f, lrow1 = 0.f;

    const uint32_t kb = (((lane & 15)) * AQSTR + (lane >> 4) * 8) * 2;

    for (int kt = 0; kt < 4; kt++) {
        // ---- scores: S = Q.K^T (single pass), 16x128 per warp ----
        float S[16][4];
#pragma unroll
        for (int f = 0; f < 16; f++)
#pragma unroll
            for (int l = 0; l < 4; l++) S[f][l] = 0.f;

#pragma unroll
        for (int j = 0; j < 8; j++) {
            const uint32_t kaddr = kb + (uint32_t)(j * 16 * AROWB);
            uint32_t Bf[4];
#pragma unroll
            for (int kf = 0; kf < 5; kf++) {
                ldsm_x4(sb + SK + kaddr + kf * 32, Bf);
                mma16816(S[2 * j + 0], Qf[kf], Bf[0], Bf[2]);
                mma16816(S[2 * j + 1], Qf[kf], Bf[1], Bf[3]);
            }
        }

        // ---- online softmax over this 128-key tile ----
        float t0 = -1e30f, t1 = -1e30f;
#pragma unroll
        for (int f = 0; f < 16; f++) {
            t0 = fmaxf(t0, fmaxf(S[f][0], S[f][1]));
            t1 = fmaxf(t1, fmaxf(S[f][2], S[f][3]));
        }
        t0 = fmaxf(t0, __shfl_xor_sync(0xffffffffu, t0, 1));
        t0 = fmaxf(t0, __shfl_xor_sync(0xffffffffu, t0, 2));
        t1 = fmaxf(t1, __shfl_xor_sync(0xffffffffu, t1, 1));
        t1 = fmaxf(t1, __shfl_xor_sync(0xffffffffu, t1, 2));

        float m0n = fmaxf(mrow0, t0);
        float m1n = fmaxf(mrow1, t1);
        float sc0 = __expf(mrow0 - m0n);
        float sc1 = __expf(mrow1 - m1n);
        mrow0 = m0n; mrow1 = m1n;

        float s0 = 0.f, s1 = 0.f;
#pragma unroll
        for (int f = 0; f < 16; f++) {
            S[f][0] = __expf(S[f][0] - m0n); s0 += S[f][0];
            S[f][1] = __expf(S[f][1] - m0n); s0 += S[f][1];
            S[f][2] = __expf(S[f][2] - m1n); s1 += S[f][2];
            S[f][3] = __expf(S[f][3] - m1n); s1 += S[f][3];
        }
        s0 += __shfl_xor_sync(0xffffffffu, s0, 1);
        s0 += __shfl_xor_sync(0xffffffffu, s0, 2);
        s1 += __shfl_xor_sync(0xffffffffu, s1, 1);
        s1 += __shfl_xor_sync(0xffffffffu, s1, 2);
        lrow0 = lrow0 * sc0 + s0;
        lrow1 = lrow1 * sc1 + s1;

#pragma unroll
        for (int f = 0; f < 10; f++) {
            O[f][0] *= sc0; O[f][1] *= sc0;
            O[f][2] *= sc1; O[f][3] *= sc1;
        }

        // ---- repack P (fp32 acc frags) -> fp16 A-operand frags ----
        uint32_t Pf[8][4];
#pragma unroll
        for (int t = 0; t < 8; t++) {
            Pf[t][0] = packh2(S[2 * t + 0][0], S[2 * t + 0][1]);
            Pf[t][1] = packh2(S[2 * t + 0][2], S[2 * t + 0][3]);
            Pf[t][2] = packh2(S[2 * t + 1][0], S[2 * t + 1][1]);
            Pf[t][3] = packh2(S[2 * t + 1][2], S[2 * t + 1][3]);
        }

        // ---- PV: O += P.V (single pass), V via trans ldmatrix ----
#pragma unroll
        for (int jn = 0; jn < 5; jn++) {
#pragma unroll
            for (int kf = 0; kf < 8; kf++) {
                const uint32_t vaddr =
                    (uint32_t)((kf * 16 + (lane & 15)) * AQSTR +
                               jn * 16 + (lane >> 4) * 8) * 2;
                uint32_t Vf[4];
                ldsm_x4_t(sb + SV + vaddr, Vf);
                mma16816(O[2 * jn + 0], Pf[kf], Vf[0], Vf[1]);
                mma16816(O[2 * jn + 1], Pf[kf], Vf[2], Vf[3]);
            }
        }

        // ---- load next K/V tile ----
        if (kt < 3) {
            __syncthreads();
            const size_t krow = segrow + (kt + 1) * 128;
#pragma unroll
            for (int i = 0; i < 5; i++) {
                int idx = i * 256 + tid;
                int rr = idx / 10, cc = idx % 10;
                uint32_t d = (uint32_t)(rr * AROWB + cc * 16);
                cp16(sb + SK + d, g_k + (krow + rr) * HDIM + cc * 8);
                cp16(sb + SV + d, g_v + (krow + rr) * HDIM + cc * 8);
            }
            asm volatile("cp.async.commit_group;");
            asm volatile("cp.async.wait_group 0;");
            __syncthreads();
        }
    }

    // ---- epilogue: O /= l, write fp16 to g_ao [s][h*80+d] ----
    const float inv0 = 1.f / lrow0;
    const float inv1 = 1.f / lrow1;
    const int row0 = g * SEGL + mt * 128 + wid * 16 + (lane >> 2);
    const int row1 = row0 + 8;
#pragma unroll
    for (int f = 0; f < 10; f++) {
        int col = h * HDIM + f * 8 + (lane & 3) * 2;
        uint32_t h0 = packh2(O[f][0] * inv0, O[f][1] * inv0);
        uint32_t h1 = packh2(O[f][2] * inv1, O[f][3] * inv1);
        *(uint32_t*)(g_ao + (size_t)row0 * DIM + col) = h0;
        *(uint32_t*)(g_ao + (size_t)row1 * DIM + col) = h1;
    }
}

// =========================================================================
// Convert fp32 -> fp16
// =========================================================================
__global__ void cvt_kernel(const float* __restrict__ x,
                           half* __restrict__ y, int n)
{
    int i = blockIdx.x * blockDim.x + threadIdx.x;
    if (i >= n) return;
    y[i] = __float2half(x[i]);
}

// =========================================================================
// RoPE + rearrange: g_qkv[s][3*1280] -> q(pre-scaled)/k/v [h*2048+s][80] fp16
// =========================================================================
__global__ void rope_kernel(const float* __restrict__ rope)
{
    int idx = blockIdx.x * blockDim.x + threadIdx.x;
    if (idx >= SEQ * NH * HDIM) return;
    int d = idx % HDIM;
    int h = (idx / HDIM) % NH;
    int s = idx / (NH * HDIM);

    float ang = rope[s * (HDIM / 2) + (d % (HDIM / 2))];
    float c, sn;
    __sincosf(ang, &sn, &c);

    const float* qrow = g_qkv + (long)s * (3 * DIM);
    int base = h * HDIM + d;
    float qv = qrow[base];
    float kv = qrow[DIM + base];
    float vv = qrow[2 * DIM + base];

    float qo, ko;
    if (d < HDIM / 2) {
        float q2 = qrow[base + HDIM / 2];
        float k2 = qrow[DIM + base + HDIM / 2];
        qo = qv * c - q2 * sn;
        ko = kv * c - k2 * sn;
    } else {
        float q2 = qrow[base - HDIM / 2];
        float k2 = qrow[DIM + base - HDIM / 2];
        qo = qv * c + q2 * sn;
        ko = kv * c + k2 * sn;
    }
    qo *= 0.11180339887498949f;   // 1/sqrt(80) folded into q

    long o = (long)(h * SEQ + s) * HDIM + d;
    g_q[o] = __float2half(qo);
    g_k[o] = __float2half(ko);
    g_v[o] = __float2half(vv);
}

// =========================================================================
extern "C" void kernel_launch(void* const* d_in, const int* in_sizes, int n_in,
                              void* d_out, int out_size)
{
    const float* hidden = (const float*)d_in[0];  // [2048,1280]
    const float* rope   = (const float*)d_in[2];  // [2048,40]
    const float* qkv_w  = (const float*)d_in[3];  // [3840,1280]
    const float* qkv_b  = (const float*)d_in[4];  // [3840]
    const float* proj_w = (const float*)d_in[5];  // [1280,1280]
    const float* proj_b = (const float*)d_in[6];  // [1280]
    float* out = (float*)d_out;                   // [2048,1280]

    float* qkv;
    cudaGetSymbolAddress((void**)&qkv, g_qkv);

    half *hid, *w1, *w2, *ao;
    cudaGetSymbolAddress((void**)&hid, g_hid);
    cudaGetSymbolAddress((void**)&w1,  g_w1);
    cudaGetSymbolAddress((void**)&w2,  g_w2);
    cudaGetSymbolAddress((void**)&ao,  g_ao);

    static int attr_set = 0;
    if (!attr_set) {
        cudaFuncSetAttribute(gemm_fp16,
                             cudaFuncAttributeMaxDynamicSharedMemorySize,
                             GEMM_SMEM);
        cudaFuncSetAttribute(attn_fused,
                             cudaFuncAttributeMaxDynamicSharedMemorySize,
                             ATT_SMEM);
        attr_set = 1;
    }

    // 0) fp32 -> fp16 conversions
    cvt_kernel<<<(SEQ * DIM + 255) / 256, 256>>>(hidden, hid, SEQ * DIM);
    cvt_kernel<<<(3 * DIM * DIM + 255) / 256, 256>>>(qkv_w, w1, 3 * DIM * DIM);
    cvt_kernel<<<(DIM * DIM + 255) / 256, 256>>>(proj_w, w2, DIM * DIM);

    // 1) QKV GEMM: [2048,1280] x [3840,1280]^T + bias -> g_qkv (fp32)
    {
        dim3 grid(3 * DIM / 128, SEQ / 128, 1);
        gemm_fp16<<<grid, 256, GEMM_SMEM>>>(hid, w1, qkv_b, qkv,
                                            DIM, DIM, DIM, 3 * DIM);
    }

    // 2) RoPE + rearrange -> q/k/v fp16 head-major
    rope_kernel<<<(SEQ * NH * HDIM + 255) / 256, 256>>>(rope);

    // 3) Fused attention: scores + softmax + PV -> g_ao (fp16)
    {
        dim3 grid(4, NSEG, NH);
        attn_fused<<<grid, 256, ATT_SMEM>>>();
    }

    // 4) Proj: [2048,1280] x [1280,1280]^T + bias -> out (fp32)
    {
        dim3 grid(DIM / 128, SEQ / 128, 1);
        gemm_fp16<<<grid, 256, GEMM_SMEM>>>(ao, w2, proj_b, out,
                                            DIM, DIM, DIM, DIM);
    }
}

// round 9
// speedup vs baseline: 3.0296x; 1.0987x over previous
#include <cuda_runtime.h>
#include <cuda_fp16.h>
#include <math.h>
#include <stdint.h>

// Problem constants: S=2048, D=1280, H=16, HD=80
// cu_seqlens = [0,512,1024,1536,2048] -> 4 segments of 512 (block-diagonal attn)
#define SEQ   2048
#define DIM   1280
#define NH    16
#define HDIM  80
#define NSEG  4
#define SEGL  512

// ---------------- device scratch (static, no allocations) ----------------
__device__ float g_qkv[SEQ * 3 * DIM];          // QKV GEMM out [s][3840] fp32
__device__ half  g_hid[SEQ * DIM];              // hidden fp16
__device__ half  g_w1[3 * DIM * DIM];           // qkv_w fp16
__device__ half  g_w2[DIM * DIM];               // proj_w fp16
__device__ half  g_q[NH * SEQ * HDIM];          // [h*2048+s][80], q pre-scaled
__device__ half  g_k[NH * SEQ * HDIM];
__device__ half  g_v[NH * SEQ * HDIM];
__device__ half  g_ao[SEQ * DIM];               // attn out [s][h*80+d] fp16

// =========================== MMA helpers =================================
__device__ __forceinline__ uint32_t smem_u32(const void* p) {
    uint32_t a;
    asm("{ .reg .u64 t; cvta.to.shared.u64 t, %1; cvt.u32.u64 %0, t; }"
        : "=r"(a) : "l"(p));
    return a;
}
__device__ __forceinline__ void ldsm_x4(uint32_t addr, uint32_t* r) {
    asm volatile("ldmatrix.sync.aligned.m8n8.x4.shared.b16 {%0,%1,%2,%3}, [%4];"
                 : "=r"(r[0]), "=r"(r[1]), "=r"(r[2]), "=r"(r[3]) : "r"(addr));
}
__device__ __forceinline__ void ldsm_x4_t(uint32_t addr, uint32_t* r) {
    asm volatile("ldmatrix.sync.aligned.m8n8.x4.trans.shared.b16 {%0,%1,%2,%3}, [%4];"
                 : "=r"(r[0]), "=r"(r[1]), "=r"(r[2]), "=r"(r[3]) : "r"(addr));
}
__device__ __forceinline__ void mma16816(float* c, const uint32_t* a,
                                         uint32_t b0, uint32_t b1) {
    asm volatile(
        "mma.sync.aligned.m16n8k16.row.col.f32.f16.f16.f32 "
        "{%0,%1,%2,%3}, {%4,%5,%6,%7}, {%8,%9}, {%0,%1,%2,%3};"
        : "+f"(c[0]), "+f"(c[1]), "+f"(c[2]), "+f"(c[3])
        : "r"(a[0]), "r"(a[1]), "r"(a[2]), "r"(a[3]), "r"(b0), "r"(b1));
}
__device__ __forceinline__ void cp16(uint32_t saddr, const void* gptr) {
    asm volatile("cp.async.ca.shared.global [%0], [%1], 16;"
                 :: "r"(saddr), "l"(gptr));
}
__device__ __forceinline__ uint32_t packh2(float x, float y) {
    __half2 h = __floats2half2_rn(x, y);
    return *reinterpret_cast<uint32_t*>(&h);
}

// =========================================================================
// fp16 TN GEMM: C[m,n] = sum_k A[m,k]*B[n,k] + bias[n]  (fp32 accum)
// CTA 128x128, BK=64, 256 threads = 8 warps (warp tile 32x64),
// 2-stage cp.async, 2 CTAs/SM. M%128==0, N%128==0, K%64==0.
// =========================================================================
#define SMROW 72                     // half per smem row (64 used + 8 pad)
#define TILEB  (128 * SMROW * 2)     // 18432 B
#define STAGEB (2 * TILEB)           // 36864 B (A + B)
#define GEMM_SMEM (2 * STAGEB)       // 73728 B

// each thread copies 64B (4 x cp16) per tile: r = tid>>1 row, hf = 64B half
#define ISSUE_STAGE(kc, st)                                               \
    do {                                                                  \
        const int      _ke = (kc) * 64;                                   \
        const uint32_t _s  = sb + (uint32_t)(st) * STAGEB + stoff;        \
        cp16(_s + 0 * TILEB,      gA + _ke);                              \
        cp16(_s + 0 * TILEB + 16, gA + _ke + 8);                          \
        cp16(_s + 0 * TILEB + 32, gA + _ke + 16);                         \
        cp16(_s + 0 * TILEB + 48, gA + _ke + 24);                         \
        cp16(_s + 1 * TILEB,      gB + _ke);                              \
        cp16(_s + 1 * TILEB + 16, gB + _ke + 8);                          \
        cp16(_s + 1 * TILEB + 32, gB + _ke + 16);                         \
        cp16(_s + 1 * TILEB + 48, gB + _ke + 24);                         \
        asm volatile("cp.async.commit_group;");                           \
    } while (0)

__global__ __launch_bounds__(256, 2)
void gemm_fp16(const half* __restrict__ A, const half* __restrict__ B,
               const float* __restrict__ bias, float* __restrict__ C,
               int K, int lda, int ldb, int ldc)
{
    extern __shared__ __align__(16) char sm[];
    const uint32_t sb = smem_u32(sm);

    const int tid  = threadIdx.x;
    const int lane = tid & 31;
    const int wid  = tid >> 5;
    const int wm   = wid & 3;
    const int wn   = wid >> 2;

    const int m0 = blockIdx.y * 128;
    const int n0 = blockIdx.x * 128;

    const int r  = tid >> 1;
    const int hf = tid & 1;             // which 32-half (64B) chunk of the row
    const half* gA = A + (size_t)(m0 + r) * lda + hf * 32;
    const half* gB = B + (size_t)(n0 + r) * ldb + hf * 32;
    const uint32_t stoff = (uint32_t)(r * SMROW + hf * 32) * 2;

    const uint32_t a_off = ((wm * 32 + (lane & 15)) * SMROW + (lane >> 4) * 8) * 2;
    const uint32_t b_off = ((wn * 64 + (lane & 15)) * SMROW + (lane >> 4) * 8) * 2;

    float acc[2][8][4];
#pragma unroll
    for (int i = 0; i < 2; i++)
#pragma unroll
        for (int j = 0; j < 8; j++)
#pragma unroll
            for (int l = 0; l < 4; l++) acc[i][j][l] = 0.f;

    const int nchunk = K >> 6;

    ISSUE_STAGE(0, 0);

    for (int kc = 0; kc < nchunk; kc++) {
        const int st = kc & 1;
        if (kc + 1 < nchunk) {
            ISSUE_STAGE(kc + 1, st ^ 1);
            asm volatile("cp.async.wait_group 1;");
        } else {
            asm volatile("cp.async.wait_group 0;");
        }
        __syncthreads();

        const uint32_t base = sb + (uint32_t)st * STAGEB;

#pragma unroll
        for (int ks = 0; ks < 4; ks++) {
            const uint32_t ko = ks * 32;   // +16 halves = 32 bytes

            uint32_t Af[2][4], Bf[4][4];
#pragma unroll
            for (int mi = 0; mi < 2; mi++)
                ldsm_x4(base + 0 * TILEB + a_off + ko + mi * (16 * SMROW * 2), Af[mi]);
#pragma unroll
            for (int njg = 0; njg < 4; njg++)
                ldsm_x4(base + 1 * TILEB + b_off + ko + njg * (16 * SMROW * 2), Bf[njg]);

#pragma unroll
            for (int mi = 0; mi < 2; mi++)
#pragma unroll
                for (int njg = 0; njg < 4; njg++) {
                    mma16816(acc[mi][2 * njg + 0], Af[mi], Bf[njg][0], Bf[njg][2]);
                    mma16816(acc[mi][2 * njg + 1], Af[mi], Bf[njg][1], Bf[njg][3]);
                }
        }
        __syncthreads();
    }

#pragma unroll
    for (int mi = 0; mi < 2; mi++) {
        int row0 = m0 + wm * 32 + mi * 16 + (lane >> 2);
#pragma unroll
        for (int nj = 0; nj < 8; nj++) {
            int col = n0 + wn * 64 + nj * 8 + (lane & 3) * 2;
            float b0 = 0.f, b1 = 0.f;
            if (bias) { b0 = bias[col]; b1 = bias[col + 1]; }
            size_t i0 = (size_t)row0 * ldc + col;
            size_t i1 = i0 + (size_t)8 * ldc;
            *(float2*)(C + i0) = make_float2(acc[mi][nj][0] + b0,
                                             acc[mi][nj][1] + b1);
            *(float2*)(C + i1) = make_float2(acc[mi][nj][2] + b0,
                                             acc[mi][nj][3] + b1);
        }
    }
}

// =========================================================================
// Fused flash attention (block-diagonal): one CTA per (h, g, 128 q-rows).
// 256 threads = 8 warps; warp w owns q-rows [w*16, w*16+16) x all 512 keys.
// fp16 MMAs, fp32 online softmax. K/V double-buffered: tile kt+1 prefetched
// via cp.async while computing on tile kt.
// =========================================================================
#define AQSTR 88                        // half per smem row (80 used + 8 pad)
#define AROWB (AQSTR * 2)               // 176 B
#define ABUF  (128 * AROWB)             // 22528 B
#define SQ    0
#define SKB(st) (ABUF * (1 + 2 * (st)))
#define SVB(st) (ABUF * (2 + 2 * (st)))
#define ATT_SMEM (5 * ABUF)             // 112640 B

__global__ __launch_bounds__(256, 1)
void attn_fused()
{
    extern __shared__ __align__(16) char sm[];
    const uint32_t sb = smem_u32(sm);

    const int tid  = threadIdx.x;
    const int lane = tid & 31;
    const int wid  = tid >> 5;

    const int mt = blockIdx.x;          // 0..3 (q tile within segment)
    const int g  = blockIdx.y;          // 0..3 (segment)
    const int h  = blockIdx.z;          // 0..15 (head)

    const size_t segrow = (size_t)(h * SEQ + g * SEGL);
    const size_t qrow0  = segrow + mt * 128;

    // per-thread K/V load mapping (128 rows x 80 half, 5 chunks of 16B each)
    const int lrr[5] = { (0 * 256 + tid) / 10, (1 * 256 + tid) / 10,
                         (2 * 256 + tid) / 10, (3 * 256 + tid) / 10,
                         (4 * 256 + tid) / 10 };
    const int lcc[5] = { (0 * 256 + tid) % 10, (1 * 256 + tid) % 10,
                         (2 * 256 + tid) % 10, (3 * 256 + tid) % 10,
                         (4 * 256 + tid) % 10 };

    // ---- prologue: load Q tile + K/V tile 0 into buffer 0 ----
#pragma unroll
    for (int i = 0; i < 5; i++) {
        uint32_t d = (uint32_t)(lrr[i] * AROWB + lcc[i] * 16);
        cp16(sb + SQ + d,     g_q + (qrow0 + lrr[i]) * HDIM + lcc[i] * 8);
        cp16(sb + SKB(0) + d, g_k + (segrow + lrr[i]) * HDIM + lcc[i] * 8);
        cp16(sb + SVB(0) + d, g_v + (segrow + lrr[i]) * HDIM + lcc[i] * 8);
    }
    asm volatile("cp.async.commit_group;");
    asm volatile("cp.async.wait_group 0;");
    __syncthreads();

    // ---- load Q fragments (persistent across k-tiles) ----
    const uint32_t aq = ((wid * 16 + (lane & 15)) * AQSTR + (lane >> 4) * 8) * 2;
    uint32_t Qf[5][4];
#pragma unroll
    for (int kf = 0; kf < 5; kf++)
        ldsm_x4(sb + SQ + aq + kf * 32, Qf[kf]);

    float O[10][4];
#pragma unroll
    for (int f = 0; f < 10; f++)
#pragma unroll
        for (int l = 0; l < 4; l++) O[f][l] = 0.f;
    float mrow0 = -1e30f, mrow1 = -1e30f;
    float lrow0 = 0.f, lrow1 = 0.f;

    const uint32_t kb = (((lane & 15)) * AQSTR + (lane >> 4) * 8) * 2;

    for (int kt = 0; kt < 4; kt++) {
        const int st = kt & 1;

        // ---- prefetch next K/V tile into the other buffer ----
        if (kt < 3) {
            const size_t krow = segrow + (kt + 1) * 128;
#pragma unroll
            for (int i = 0; i < 5; i++) {
                uint32_t d = (uint32_t)(lrr[i] * AROWB + lcc[i] * 16);
                cp16(sb + SKB(st ^ 1) + d, g_k + (krow + lrr[i]) * HDIM + lcc[i] * 8);
                cp16(sb + SVB(st ^ 1) + d, g_v + (krow + lrr[i]) * HDIM + lcc[i] * 8);
            }
            asm volatile("cp.async.commit_group;");
            asm volatile("cp.async.wait_group 1;");
        } else {
            asm volatile("cp.async.wait_group 0;");
        }
        __syncthreads();

        // ---- scores: S = Q.K^T, 16x128 per warp ----
        float S[16][4];
#pragma unroll
        for (int f = 0; f < 16; f++)
#pragma unroll
            for (int l = 0; l < 4; l++) S[f][l] = 0.f;

#pragma unroll
        for (int j = 0; j < 8; j++) {
            const uint32_t kaddr = sb + SKB(st) + kb + (uint32_t)(j * 16 * AROWB);
            uint32_t Bf[4];
#pragma unroll
            for (int kf = 0; kf < 5; kf++) {
                ldsm_x4(kaddr + kf * 32, Bf);
                mma16816(S[2 * j + 0], Qf[kf], Bf[0], Bf[2]);
                mma16816(S[2 * j + 1], Qf[kf], Bf[1], Bf[3]);
            }
        }

        // ---- online softmax ----
        float t0 = -1e30f, t1 = -1e30f;
#pragma unroll
        for (int f = 0; f < 16; f++) {
            t0 = fmaxf(t0, fmaxf(S[f][0], S[f][1]));
            t1 = fmaxf(t1, fmaxf(S[f][2], S[f][3]));
        }
        t0 = fmaxf(t0, __shfl_xor_sync(0xffffffffu, t0, 1));
        t0 = fmaxf(t0, __shfl_xor_sync(0xffffffffu, t0, 2));
        t1 = fmaxf(t1, __shfl_xor_sync(0xffffffffu, t1, 1));
        t1 = fmaxf(t1, __shfl_xor_sync(0xffffffffu, t1, 2));

        float m0n = fmaxf(mrow0, t0);
        float m1n = fmaxf(mrow1, t1);
        float sc0 = __expf(mrow0 - m0n);
        float sc1 = __expf(mrow1 - m1n);
        mrow0 = m0n; mrow1 = m1n;

        float s0 = 0.f, s1 = 0.f;
#pragma unroll
        for (int f = 0; f < 16; f++) {
            S[f][0] = __expf(S[f][0] - m0n); s0 += S[f][0];
            S[f][1] = __expf(S[f][1] - m0n); s0 += S[f][1];
            S[f][2] = __expf(S[f][2] - m1n); s1 += S[f][2];
            S[f][3] = __expf(S[f][3] - m1n); s1 += S[f][3];
        }
        s0 += __shfl_xor_sync(0xffffffffu, s0, 1);
        s0 += __shfl_xor_sync(0xffffffffu, s0, 2);
        s1 += __shfl_xor_sync(0xffffffffu, s1, 1);
        s1 += __shfl_xor_sync(0xffffffffu, s1, 2);
        lrow0 = lrow0 * sc0 + s0;
        lrow1 = lrow1 * sc1 + s1;

#pragma unroll
        for (int f = 0; f < 10; f++) {
            O[f][0] *= sc0; O[f][1] *= sc0;
            O[f][2] *= sc1; O[f][3] *= sc1;
        }

        // ---- repack P -> fp16 A-operand frags ----
        uint32_t Pf[8][4];
#pragma unroll
        for (int t = 0; t < 8; t++) {
            Pf[t][0] = packh2(S[2 * t + 0][0], S[2 * t + 0][1]);
            Pf[t][1] = packh2(S[2 * t + 0][2], S[2 * t + 0][3]);
            Pf[t][2] = packh2(S[2 * t + 1][0], S[2 * t + 1][1]);
            Pf[t][3] = packh2(S[2 * t + 1][2], S[2 * t + 1][3]);
        }

        // ---- PV: O += P.V, V via trans ldmatrix ----
#pragma unroll
        for (int jn = 0; jn < 5; jn++) {
#pragma unroll
            for (int kf = 0; kf < 8; kf++) {
                const uint32_t vaddr = sb + SVB(st) +
                    (uint32_t)((kf * 16 + (lane & 15)) * AQSTR +
                               jn * 16 + (lane >> 4) * 8) * 2;
                uint32_t Vf[4];
                ldsm_x4_t(vaddr, Vf);
                mma16816(O[2 * jn + 0], Pf[kf], Vf[0], Vf[1]);
                mma16816(O[2 * jn + 1], Pf[kf], Vf[2], Vf[3]);
            }
        }

        if (kt < 3) __syncthreads();   // protect buffer st^1 (written next iter)
    }

    // ---- epilogue ----
    const float inv0 = 1.f / lrow0;
    const float inv1 = 1.f / lrow1;
    const int row0 = g * SEGL + mt * 128 + wid * 16 + (lane >> 2);
    const int row1 = row0 + 8;
#pragma unroll
    for (int f = 0; f < 10; f++) {
        int col = h * HDIM + f * 8 + (lane & 3) * 2;
        uint32_t h0 = packh2(O[f][0] * inv0, O[f][1] * inv0);
        uint32_t h1 = packh2(O[f][2] * inv1, O[f][3] * inv1);
        *(uint32_t*)(g_ao + (size_t)row0 * DIM + col) = h0;
        *(uint32_t*)(g_ao + (size_t)row1 * DIM + col) = h1;
    }
}

// =========================================================================
// Convert fp32 -> fp16
// =========================================================================
__global__ void cvt_kernel(const float* __restrict__ x,
                           half* __restrict__ y, int n)
{
    int i = blockIdx.x * blockDim.x + threadIdx.x;
    if (i >= n) return;
    y[i] = __float2half(x[i]);
}

// =========================================================================
// RoPE + rearrange: g_qkv[s][3*1280] -> q(pre-scaled)/k/v [h*2048+s][80] fp16
// =========================================================================
__global__ void rope_kernel(const float* __restrict__ rope)
{
    int idx = blockIdx.x * blockDim.x + threadIdx.x;
    if (idx >= SEQ * NH * HDIM) return;
    int d = idx % HDIM;
    int h = (idx / HDIM) % NH;
    int s = idx / (NH * HDIM);

    float ang = rope[s * (HDIM / 2) + (d % (HDIM / 2))];
    float c, sn;
    __sincosf(ang, &sn, &c);

    const float* qrow = g_qkv + (long)s * (3 * DIM);
    int base = h * HDIM + d;
    float qv = qrow[base];
    float kv = qrow[DIM + base];
    float vv = qrow[2 * DIM + base];

    float qo, ko;
    if (d < HDIM / 2) {
        float q2 = qrow[base + HDIM / 2];
        float k2 = qrow[DIM + base + HDIM / 2];
        qo = qv * c - q2 * sn;
        ko = kv * c - k2 * sn;
    } else {
        float q2 = qrow[base - HDIM / 2];
        float k2 = qrow[DIM + base - HDIM / 2];
        qo = qv * c + q2 * sn;
        ko = kv * c + k2 * sn;
    }
    qo *= 0.11180339887498949f;   // 1/sqrt(80) folded into q

    long o = (long)(h * SEQ + s) * HDIM + d;
    g_q[o] = __float2half(qo);
    g_k[o] = __float2half(ko);
    g_v[o] = __float2half(vv);
}

// =========================================================================
extern "C" void kernel_launch(void* const* d_in, const int* in_sizes, int n_in,
                              void* d_out, int out_size)
{
    const float* hidden = (const float*)d_in[0];  // [2048,1280]
    const float* rope   = (const float*)d_in[2];  // [2048,40]
    const float* qkv_w  = (const float*)d_in[3];  // [3840,1280]
    const float* qkv_b  = (const float*)d_in[4];  // [3840]
    const float* proj_w = (const float*)d_in[5];  // [1280,1280]
    const float* proj_b = (const float*)d_in[6];  // [1280]
    float* out = (float*)d_out;                   // [2048,1280]

    float* qkv;
    cudaGetSymbolAddress((void**)&qkv, g_qkv);

    half *hid, *w1, *w2, *ao;
    cudaGetSymbolAddress((void**)&hid, g_hid);
    cudaGetSymbolAddress((void**)&w1,  g_w1);
    cudaGetSymbolAddress((void**)&w2,  g_w2);
    cudaGetSymbolAddress((void**)&ao,  g_ao);

    static int attr_set = 0;
    if (!attr_set) {
        cudaFuncSetAttribute(gemm_fp16,
                             cudaFuncAttributeMaxDynamicSharedMemorySize,
                             GEMM_SMEM);
        cudaFuncSetAttribute(attn_fused,
                             cudaFuncAttributeMaxDynamicSharedMemorySize,
                             ATT_SMEM);
        attr_set = 1;
    }

    // 0) fp32 -> fp16 conversions
    cvt_kernel<<<(SEQ * DIM + 255) / 256, 256>>>(hidden, hid, SEQ * DIM);
    cvt_kernel<<<(3 * DIM * DIM + 255) / 256, 256>>>(qkv_w, w1, 3 * DIM * DIM);
    cvt_kernel<<<(DIM * DIM + 255) / 256, 256>>>(proj_w, w2, DIM * DIM);

    // 1) QKV GEMM: [2048,1280] x [3840,1280]^T + bias -> g_qkv (fp32)
    {
        dim3 grid(3 * DIM / 128, SEQ / 128, 1);
        gemm_fp16<<<grid, 256, GEMM_SMEM>>>(hid, w1, qkv_b, qkv,
                                            DIM, DIM, DIM, 3 * DIM);
    }

    // 2) RoPE + rearrange -> q/k/v fp16 head-major
    rope_kernel<<<(SEQ * NH * HDIM + 255) / 256, 256>>>(rope);

    // 3) Fused attention: scores + softmax + PV -> g_ao (fp16)
    {
        dim3 grid(4, NSEG, NH);
        attn_fused<<<grid, 256, ATT_SMEM>>>();
    }

    // 4) Proj: [2048,1280] x [1280,1280]^T + bias -> out (fp32)
    {
        dim3 grid(DIM / 128, SEQ / 128, 1);
        gemm_fp16<<<grid, 256, GEMM_SMEM>>>(ao, w2, proj_b, out,
                                            DIM, DIM, DIM, DIM);
    }
}

// round 10
// speedup vs baseline: 3.2662x; 1.0781x over previous
#include <cuda_runtime.h>
#include <cuda_fp16.h>
#include <math.h>
#include <stdint.h>

// Problem constants: S=2048, D=1280, H=16, HD=80
// cu_seqlens = [0,512,1024,1536,2048] -> 4 segments of 512 (block-diagonal attn)
#define SEQ   2048
#define DIM   1280
#define NH    16
#define HDIM  80
#define NSEG  4
#define SEGL  512

// ---------------- device scratch (static, no allocations) ----------------
__device__ half  g_qkv[SEQ * 3 * DIM];          // QKV GEMM out [s][3840] fp16
__device__ half  g_hid[SEQ * DIM];              // hidden fp16
__device__ half  g_w1[3 * DIM * DIM];           // qkv_w fp16
__device__ half  g_w2[DIM * DIM];               // proj_w fp16
__device__ half  g_q[NH * SEQ * HDIM];          // [h*2048+s][80], q pre-scaled
__device__ half  g_k[NH * SEQ * HDIM];
__device__ half  g_v[NH * SEQ * HDIM];
__device__ half  g_ao[SEQ * DIM];               // attn out [s][h*80+d] fp16

// =========================== MMA helpers =================================
__device__ __forceinline__ uint32_t smem_u32(const void* p) {
    uint32_t a;
    asm("{ .reg .u64 t; cvta.to.shared.u64 t, %1; cvt.u32.u64 %0, t; }"
        : "=r"(a) : "l"(p));
    return a;
}
__device__ __forceinline__ void ldsm_x4(uint32_t addr, uint32_t* r) {
    asm volatile("ldmatrix.sync.aligned.m8n8.x4.shared.b16 {%0,%1,%2,%3}, [%4];"
                 : "=r"(r[0]), "=r"(r[1]), "=r"(r[2]), "=r"(r[3]) : "r"(addr));
}
__device__ __forceinline__ void ldsm_x4_t(uint32_t addr, uint32_t* r) {
    asm volatile("ldmatrix.sync.aligned.m8n8.x4.trans.shared.b16 {%0,%1,%2,%3}, [%4];"
                 : "=r"(r[0]), "=r"(r[1]), "=r"(r[2]), "=r"(r[3]) : "r"(addr));
}
__device__ __forceinline__ void mma16816(float* c, const uint32_t* a,
                                         uint32_t b0, uint32_t b1) {
    asm volatile(
        "mma.sync.aligned.m16n8k16.row.col.f32.f16.f16.f32 "
        "{%0,%1,%2,%3}, {%4,%5,%6,%7}, {%8,%9}, {%0,%1,%2,%3};"
        : "+f"(c[0]), "+f"(c[1]), "+f"(c[2]), "+f"(c[3])
        : "r"(a[0]), "r"(a[1]), "r"(a[2]), "r"(a[3]), "r"(b0), "r"(b1));
}
__device__ __forceinline__ void cp16(uint32_t saddr, const void* gptr) {
    asm volatile("cp.async.ca.shared.global [%0], [%1], 16;"
                 :: "r"(saddr), "l"(gptr));
}
__device__ __forceinline__ uint32_t packh2(float x, float y) {
    __half2 h = __floats2half2_rn(x, y);
    return *reinterpret_cast<uint32_t*>(&h);
}

// =========================================================================
// fp16 TN GEMM: C[m,n] = sum_k A[m,k]*B[n,k] + bias[n]  (fp32 accum)
// CTA 128x128, BK=64, 256 threads = 8 warps (warp tile 32x64),
// 2-stage cp.async, 2 CTAs/SM, fragment-level software pipelining.
// Output: fp32 to C (if Ch==nullptr) else fp16 to Ch.
// =========================================================================
#define SMROW 72                     // half per smem row (64 used + 8 pad)
#define TILEB  (128 * SMROW * 2)     // 18432 B
#define STAGEB (2 * TILEB)           // 36864 B (A + B)
#define GEMM_SMEM (2 * STAGEB)       // 73728 B

#define ISSUE_STAGE(kc, st)                                               \
    do {                                                                  \
        const int      _ke = (kc) * 64;                                   \
        const uint32_t _s  = sb + (uint32_t)(st) * STAGEB + stoff;        \
        cp16(_s + 0 * TILEB,      gA + _ke);                              \
        cp16(_s + 0 * TILEB + 16, gA + _ke + 8);                          \
        cp16(_s + 0 * TILEB + 32, gA + _ke + 16);                         \
        cp16(_s + 0 * TILEB + 48, gA + _ke + 24);                         \
        cp16(_s + 1 * TILEB,      gB + _ke);                              \
        cp16(_s + 1 * TILEB + 16, gB + _ke + 8);                          \
        cp16(_s + 1 * TILEB + 32, gB + _ke + 16);                         \
        cp16(_s + 1 * TILEB + 48, gB + _ke + 24);                         \
        asm volatile("cp.async.commit_group;");                           \
    } while (0)

#define LOAD_FRAGS(buf, base, ko)                                         \
    do {                                                                  \
        _Pragma("unroll")                                                 \
        for (int _mi = 0; _mi < 2; _mi++)                                 \
            ldsm_x4((base) + 0 * TILEB + a_off + (ko) +                   \
                    _mi * (16 * SMROW * 2), Af[buf][_mi]);                \
        _Pragma("unroll")                                                 \
        for (int _nj = 0; _nj < 4; _nj++)                                 \
            ldsm_x4((base) + 1 * TILEB + b_off + (ko) +                   \
                    _nj * (16 * SMROW * 2), Bf[buf][_nj]);                \
    } while (0)

__global__ __launch_bounds__(256, 2)
void gemm_fp16(const half* __restrict__ A, const half* __restrict__ B,
               const float* __restrict__ bias, float* __restrict__ C,
               half* __restrict__ Ch,
               int K, int lda, int ldb, int ldc)
{
    extern __shared__ __align__(16) char sm[];
    const uint32_t sb = smem_u32(sm);

    const int tid  = threadIdx.x;
    const int lane = tid & 31;
    const int wid  = tid >> 5;
    const int wm   = wid & 3;
    const int wn   = wid >> 2;

    const int m0 = blockIdx.y * 128;
    const int n0 = blockIdx.x * 128;

    const int r  = tid >> 1;
    const int hf = tid & 1;
    const half* gA = A + (size_t)(m0 + r) * lda + hf * 32;
    const half* gB = B + (size_t)(n0 + r) * ldb + hf * 32;
    const uint32_t stoff = (uint32_t)(r * SMROW + hf * 32) * 2;

    const uint32_t a_off = ((wm * 32 + (lane & 15)) * SMROW + (lane >> 4) * 8) * 2;
    const uint32_t b_off = ((wn * 64 + (lane & 15)) * SMROW + (lane >> 4) * 8) * 2;

    float acc[2][8][4];
#pragma unroll
    for (int i = 0; i < 2; i++)
#pragma unroll
        for (int j = 0; j < 8; j++)
#pragma unroll
            for (int l = 0; l < 4; l++) acc[i][j][l] = 0.f;

    const int nchunk = K >> 6;

    uint32_t Af[2][2][4], Bf[2][4][4];    // double-buffered fragments

    ISSUE_STAGE(0, 0);

    for (int kc = 0; kc < nchunk; kc++) {
        const int st = kc & 1;
        if (kc + 1 < nchunk) {
            ISSUE_STAGE(kc + 1, st ^ 1);
            asm volatile("cp.async.wait_group 1;");
        } else {
            asm volatile("cp.async.wait_group 0;");
        }
        __syncthreads();

        const uint32_t base = sb + (uint32_t)st * STAGEB;

        LOAD_FRAGS(0, base, 0);           // preload frags for ks=0

#pragma unroll
        for (int ks = 0; ks < 4; ks++) {
            const int cur = ks & 1;
            if (ks < 3)
                LOAD_FRAGS(cur ^ 1, base, (ks + 1) * 32);

#pragma unroll
            for (int mi = 0; mi < 2; mi++)
#pragma unroll
                for (int njg = 0; njg < 4; njg++) {
                    mma16816(acc[mi][2 * njg + 0], Af[cur][mi],
                             Bf[cur][njg][0], Bf[cur][njg][2]);
                    mma16816(acc[mi][2 * njg + 1], Af[cur][mi],
                             Bf[cur][njg][1], Bf[cur][njg][3]);
                }
        }
        __syncthreads();
    }

#pragma unroll
    for (int mi = 0; mi < 2; mi++) {
        int row0 = m0 + wm * 32 + mi * 16 + (lane >> 2);
#pragma unroll
        for (int nj = 0; nj < 8; nj++) {
            int col = n0 + wn * 64 + nj * 8 + (lane & 3) * 2;
            float b0 = 0.f, b1 = 0.f;
            if (bias) { b0 = bias[col]; b1 = bias[col + 1]; }
            size_t i0 = (size_t)row0 * ldc + col;
            size_t i1 = i0 + (size_t)8 * ldc;
            float v00 = acc[mi][nj][0] + b0, v01 = acc[mi][nj][1] + b1;
            float v10 = acc[mi][nj][2] + b0, v11 = acc[mi][nj][3] + b1;
            if (Ch) {
                *(uint32_t*)(Ch + i0) = packh2(v00, v01);
                *(uint32_t*)(Ch + i1) = packh2(v10, v11);
            } else {
                *(float2*)(C + i0) = make_float2(v00, v01);
                *(float2*)(C + i1) = make_float2(v10, v11);
            }
        }
    }
}

// =========================================================================
// Fused flash attention (block-diagonal): one CTA per (h, g, 128 q-rows).
// 256 threads = 8 warps; warp w owns q-rows [w*16, w*16+16) x all 512 keys.
// fp16 MMAs, fp32 online softmax, K/V double-buffered via cp.async.
// =========================================================================
#define AQSTR 88                        // half per smem row (80 used + 8 pad)
#define AROWB (AQSTR * 2)               // 176 B
#define ABUF  (128 * AROWB)             // 22528 B
#define SQ    0
#define SKB(st) (ABUF * (1 + 2 * (st)))
#define SVB(st) (ABUF * (2 + 2 * (st)))
#define ATT_SMEM (5 * ABUF)             // 112640 B

__global__ __launch_bounds__(256, 1)
void attn_fused()
{
    extern __shared__ __align__(16) char sm[];
    const uint32_t sb = smem_u32(sm);

    const int tid  = threadIdx.x;
    const int lane = tid & 31;
    const int wid  = tid >> 5;

    const int mt = blockIdx.x;
    const int g  = blockIdx.y;
    const int h  = blockIdx.z;

    const size_t segrow = (size_t)(h * SEQ + g * SEGL);
    const size_t qrow0  = segrow + mt * 128;

    const int lrr[5] = { (0 * 256 + tid) / 10, (1 * 256 + tid) / 10,
                         (2 * 256 + tid) / 10, (3 * 256 + tid) / 10,
                         (4 * 256 + tid) / 10 };
    const int lcc[5] = { (0 * 256 + tid) % 10, (1 * 256 + tid) % 10,
                         (2 * 256 + tid) % 10, (3 * 256 + tid) % 10,
                         (4 * 256 + tid) % 10 };

#pragma unroll
    for (int i = 0; i < 5; i++) {
        uint32_t d = (uint32_t)(lrr[i] * AROWB + lcc[i] * 16);
        cp16(sb + SQ + d,     g_q + (qrow0 + lrr[i]) * HDIM + lcc[i] * 8);
        cp16(sb + SKB(0) + d, g_k + (segrow + lrr[i]) * HDIM + lcc[i] * 8);
        cp16(sb + SVB(0) + d, g_v + (segrow + lrr[i]) * HDIM + lcc[i] * 8);
    }
    asm volatile("cp.async.commit_group;");
    asm volatile("cp.async.wait_group 0;");
    __syncthreads();

    const uint32_t aq = ((wid * 16 + (lane & 15)) * AQSTR + (lane >> 4) * 8) * 2;
    uint32_t Qf[5][4];
#pragma unroll
    for (int kf = 0; kf < 5; kf++)
        ldsm_x4(sb + SQ + aq + kf * 32, Qf[kf]);

    float O[10][4];
#pragma unroll
    for (int f = 0; f < 10; f++)
#pragma unroll
        for (int l = 0; l < 4; l++) O[f][l] = 0.f;
    float mrow0 = -1e30f, mrow1 = -1e30f;
    float lrow0 = 0.f, lrow1 = 0.f;

    const uint32_t kb = (((lane & 15)) * AQSTR + (lane >> 4) * 8) * 2;

    for (int kt = 0; kt < 4; kt++) {
        const int st = kt & 1;

        if (kt < 3) {
            const size_t krow = segrow + (kt + 1) * 128;
#pragma unroll
            for (int i = 0; i < 5; i++) {
                uint32_t d = (uint32_t)(lrr[i] * AROWB + lcc[i] * 16);
                cp16(sb + SKB(st ^ 1) + d, g_k + (krow + lrr[i]) * HDIM + lcc[i] * 8);
                cp16(sb + SVB(st ^ 1) + d, g_v + (krow + lrr[i]) * HDIM + lcc[i] * 8);
            }
            asm volatile("cp.async.commit_group;");
            asm volatile("cp.async.wait_group 1;");
        } else {
            asm volatile("cp.async.wait_group 0;");
        }
        __syncthreads();

        float S[16][4];
#pragma unroll
        for (int f = 0; f < 16; f++)
#pragma unroll
            for (int l = 0; l < 4; l++) S[f][l] = 0.f;

#pragma unroll
        for (int j = 0; j < 8; j++) {
            const uint32_t kaddr = sb + SKB(st) + kb + (uint32_t)(j * 16 * AROWB);
            uint32_t Bf[4];
#pragma unroll
            for (int kf = 0; kf < 5; kf++) {
                ldsm_x4(kaddr + kf * 32, Bf);
                mma16816(S[2 * j + 0], Qf[kf], Bf[0], Bf[2]);
                mma16816(S[2 * j + 1], Qf[kf], Bf[1], Bf[3]);
            }
        }

        float t0 = -1e30f, t1 = -1e30f;
#pragma unroll
        for (int f = 0; f < 16; f++) {
            t0 = fmaxf(t0, fmaxf(S[f][0], S[f][1]));
            t1 = fmaxf(t1, fmaxf(S[f][2], S[f][3]));
        }
        t0 = fmaxf(t0, __shfl_xor_sync(0xffffffffu, t0, 1));
        t0 = fmaxf(t0, __shfl_xor_sync(0xffffffffu, t0, 2));
        t1 = fmaxf(t1, __shfl_xor_sync(0xffffffffu, t1, 1));
        t1 = fmaxf(t1, __shfl_xor_sync(0xffffffffu, t1, 2));

        float m0n = fmaxf(mrow0, t0);
        float m1n = fmaxf(mrow1, t1);
        float sc0 = __expf(mrow0 - m0n);
        float sc1 = __expf(mrow1 - m1n);
        mrow0 = m0n; mrow1 = m1n;

        float s0 = 0.f, s1 = 0.f;
#pragma unroll
        for (int f = 0; f < 16; f++) {
            S[f][0] = __expf(S[f][0] - m0n); s0 += S[f][0];
            S[f][1] = __expf(S[f][1] - m0n); s0 += S[f][1];
            S[f][2] = __expf(S[f][2] - m1n); s1 += S[f][2];
            S[f][3] = __expf(S[f][3] - m1n); s1 += S[f][3];
        }
        s0 += __shfl_xor_sync(0xffffffffu, s0, 1);
        s0 += __shfl_xor_sync(0xffffffffu, s0, 2);
        s1 += __shfl_xor_sync(0xffffffffu, s1, 1);
        s1 += __shfl_xor_sync(0xffffffffu, s1, 2);
        lrow0 = lrow0 * sc0 + s0;
        lrow1 = lrow1 * sc1 + s1;

#pragma unroll
        for (int f = 0; f < 10; f++) {
            O[f][0] *= sc0; O[f][1] *= sc0;
            O[f][2] *= sc1; O[f][3] *= sc1;
        }

        uint32_t Pf[8][4];
#pragma unroll
        for (int t = 0; t < 8; t++) {
            Pf[t][0] = packh2(S[2 * t + 0][0], S[2 * t + 0][1]);
            Pf[t][1] = packh2(S[2 * t + 0][2], S[2 * t + 0][3]);
            Pf[t][2] = packh2(S[2 * t + 1][0], S[2 * t + 1][1]);
            Pf[t][3] = packh2(S[2 * t + 1][2], S[2 * t + 1][3]);
        }

#pragma unroll
        for (int jn = 0; jn < 5; jn++) {
#pragma unroll
            for (int kf = 0; kf < 8; kf++) {
                const uint32_t vaddr = sb + SVB(st) +
                    (uint32_t)((kf * 16 + (lane & 15)) * AQSTR +
                               jn * 16 + (lane >> 4) * 8) * 2;
                uint32_t Vf[4];
                ldsm_x4_t(vaddr, Vf);
                mma16816(O[2 * jn + 0], Pf[kf], Vf[0], Vf[1]);
                mma16816(O[2 * jn + 1], Pf[kf], Vf[2], Vf[3]);
            }
        }

        if (kt < 3) __syncthreads();
    }

    const float inv0 = 1.f / lrow0;
    const float inv1 = 1.f / lrow1;
    const int row0 = g * SEGL + mt * 128 + wid * 16 + (lane >> 2);
    const int row1 = row0 + 8;
#pragma unroll
    for (int f = 0; f < 10; f++) {
        int col = h * HDIM + f * 8 + (lane & 3) * 2;
        *(uint32_t*)(g_ao + (size_t)row0 * DIM + col) =
            packh2(O[f][0] * inv0, O[f][1] * inv0);
        *(uint32_t*)(g_ao + (size_t)row1 * DIM + col) =
            packh2(O[f][2] * inv1, O[f][3] * inv1);
    }
}

// =========================================================================
// Convert fp32 -> fp16 (vectorized x4)
// =========================================================================
__global__ void cvt_kernel(const float* __restrict__ x,
                           half* __restrict__ y, int n)
{
    int i = (blockIdx.x * blockDim.x + threadIdx.x) * 4;
    if (i >= n) return;
    float4 v = *(const float4*)(x + i);
    uint32_t h0 = packh2(v.x, v.y);
    uint32_t h1 = packh2(v.z, v.w);
    *(uint32_t*)(y + i)     = h0;
    *(uint32_t*)(y + i + 2) = h1;
}

// =========================================================================
// RoPE + rearrange: g_qkv[s][3*1280] fp16 -> q(pre-scaled)/k/v [h*2048+s][80]
// =========================================================================
__global__ void rope_kernel(const float* __restrict__ rope)
{
    int idx = blockIdx.x * blockDim.x + threadIdx.x;
    if (idx >= SEQ * NH * HDIM) return;
    int d = idx % HDIM;
    int h = (idx / HDIM) % NH;
    int s = idx / (NH * HDIM);

    float ang = rope[s * (HDIM / 2) + (d % (HDIM / 2))];
    float c, sn;
    __sincosf(ang, &sn, &c);

    const half* qrow = g_qkv + (long)s * (3 * DIM);
    int base = h * HDIM + d;
    float qv = __half2float(qrow[base]);
    float kv = __half2float(qrow[DIM + base]);
    float vv = __half2float(qrow[2 * DIM + base]);

    float qo, ko;
    if (d < HDIM / 2) {
        float q2 = __half2float(qrow[base + HDIM / 2]);
        float k2 = __half2float(qrow[DIM + base + HDIM / 2]);
        qo = qv * c - q2 * sn;
        ko = kv * c - k2 * sn;
    } else {
        float q2 = __half2float(qrow[base - HDIM / 2]);
        float k2 = __half2float(qrow[DIM + base - HDIM / 2]);
        qo = qv * c + q2 * sn;
        ko = kv * c + k2 * sn;
    }
    qo *= 0.11180339887498949f;   // 1/sqrt(80) folded into q

    long o = (long)(h * SEQ + s) * HDIM + d;
    g_q[o] = __float2half(qo);
    g_k[o] = __float2half(ko);
    g_v[o] = __float2half(vv);
}

// =========================================================================
extern "C" void kernel_launch(void* const* d_in, const int* in_sizes, int n_in,
                              void* d_out, int out_size)
{
    const float* hidden = (const float*)d_in[0];  // [2048,1280]
    const float* rope   = (const float*)d_in[2];  // [2048,40]
    const float* qkv_w  = (const float*)d_in[3];  // [3840,1280]
    const float* qkv_b  = (const float*)d_in[4];  // [3840]
    const float* proj_w = (const float*)d_in[5];  // [1280,1280]
    const float* proj_b = (const float*)d_in[6];  // [1280]
    float* out = (float*)d_out;                   // [2048,1280]

    half *qkv, *hid, *w1, *w2, *ao;
    cudaGetSymbolAddress((void**)&qkv, g_qkv);
    cudaGetSymbolAddress((void**)&hid, g_hid);
    cudaGetSymbolAddress((void**)&w1,  g_w1);
    cudaGetSymbolAddress((void**)&w2,  g_w2);
    cudaGetSymbolAddress((void**)&ao,  g_ao);

    static int attr_set = 0;
    if (!attr_set) {
        cudaFuncSetAttribute(gemm_fp16,
                             cudaFuncAttributeMaxDynamicSharedMemorySize,
                             GEMM_SMEM);
        cudaFuncSetAttribute(attn_fused,
                             cudaFuncAttributeMaxDynamicSharedMemorySize,
                             ATT_SMEM);
        attr_set = 1;
    }

    // 0) fp32 -> fp16 conversions
    cvt_kernel<<<(SEQ * DIM / 4 + 255) / 256, 256>>>(hidden, hid, SEQ * DIM);
    cvt_kernel<<<(3 * DIM * DIM / 4 + 255) / 256, 256>>>(qkv_w, w1, 3 * DIM * DIM);
    cvt_kernel<<<(DIM * DIM / 4 + 255) / 256, 256>>>(proj_w, w2, DIM * DIM);

    // 1) QKV GEMM: [2048,1280] x [3840,1280]^T + bias -> g_qkv (fp16)
    {
        dim3 grid(3 * DIM / 128, SEQ / 128, 1);
        gemm_fp16<<<grid, 256, GEMM_SMEM>>>(hid, w1, qkv_b, nullptr, qkv,
                                            DIM, DIM, DIM, 3 * DIM);
    }

    // 2) RoPE + rearrange -> q/k/v fp16 head-major
    rope_kernel<<<(SEQ * NH * HDIM + 255) / 256, 256>>>(rope);

    // 3) Fused attention: scores + softmax + PV -> g_ao (fp16)
    {
        dim3 grid(4, NSEG, NH);
        attn_fused<<<grid, 256, ATT_SMEM>>>();
    }

    // 4) Proj: [2048,1280] x [1280,1280]^T + bias -> out (fp32)
    {
        dim3 grid(DIM / 128, SEQ / 128, 1);
        gemm_fp16<<<grid, 256, GEMM_SMEM>>>(ao, w2, proj_b, out, nullptr,
                                            DIM, DIM, DIM, DIM);
    }
}